// round 2
// baseline (speedup 1.0000x reference)
#include <cuda_runtime.h>
#include <math.h>

// ---------------- Problem dims (fixed) ----------------
#define T_TOK   8192          // B*S tokens
#define D_DIM   2048
#define M_DIM   1024
#define E_NUM   8
#define TOPK    2
#define NCOPIES (T_TOK*TOPK)  // 16384

// ---------------- Scratch (static device globals; no allocation) ----------------
__device__ int   g_counts[E_NUM];
__device__ int   g_offsets[E_NUM + 1];
__device__ int   g_cursor[E_NUM];
__device__ int   g_expert[NCOPIES];
__device__ float g_weight[NCOPIES];
__device__ int   g_pos[NCOPIES];          // (t,k) -> sorted row
__device__ int   g_row2tok[NCOPIES];      // sorted row -> token
__device__ float g_inter[(size_t)NCOPIES * M_DIM];      // 64 MB
__device__ float g_outsorted[(size_t)NCOPIES * D_DIM];  // 128 MB

// ---------------- packed f32x2 helpers (Blackwell) ----------------
__device__ __forceinline__ unsigned long long pack2(float a, float b) {
    unsigned long long r;
    asm("mov.b64 %0, {%1, %2};" : "=l"(r) : "f"(a), "f"(b));
    return r;
}
__device__ __forceinline__ void fma2(unsigned long long& d, unsigned long long a, unsigned long long b) {
    asm("fma.rn.f32x2 %0, %1, %2, %3;" : "=l"(d) : "l"(a), "l"(b), "l"(d));
}
__device__ __forceinline__ void unpack2(float& lo, float& hi, unsigned long long v) {
    asm("mov.b64 {%0, %1}, %2;" : "=f"(lo), "=f"(hi) : "l"(v));
}

// ---------------- 0: zero counters ----------------
__global__ void init_k() {
    int i = threadIdx.x;
    if (i < E_NUM) { g_counts[i] = 0; g_cursor[i] = 0; }
}

// ---------------- 1: router (logits + top2 + softmax + counts) ----------------
__global__ void router_k(const float* __restrict__ x, const float* __restrict__ wg) {
    int warp = threadIdx.x >> 5, lane = threadIdx.x & 31;
    int t = blockIdx.x * 8 + warp;
    if (t >= T_TOK) return;
    const float* xr = x + (size_t)t * D_DIM;

    float acc[E_NUM];
#pragma unroll
    for (int e = 0; e < E_NUM; e++) acc[e] = 0.f;

    for (int d = lane; d < D_DIM; d += 32) {
        float xv = xr[d];
        const float* w = wg + (size_t)d * E_NUM;
#pragma unroll
        for (int e = 0; e < E_NUM; e++) acc[e] = fmaf(xv, w[e], acc[e]);
    }
#pragma unroll
    for (int e = 0; e < E_NUM; e++) {
#pragma unroll
        for (int o = 16; o > 0; o >>= 1) acc[e] += __shfl_xor_sync(0xffffffffu, acc[e], o);
    }
    if (lane == 0) {
        int e0 = 0; float l0 = acc[0];
#pragma unroll
        for (int e = 1; e < E_NUM; e++) if (acc[e] > l0) { l0 = acc[e]; e0 = e; }
        int e1 = -1; float l1 = -INFINITY;
#pragma unroll
        for (int e = 0; e < E_NUM; e++) if (e != e0 && acc[e] > l1) { l1 = acc[e]; e1 = e; }
        float w0 = 1.f / (1.f + expf(l1 - l0));
        float w1 = 1.f - w0;
        g_expert[t * 2 + 0] = e0; g_expert[t * 2 + 1] = e1;
        g_weight[t * 2 + 0] = w0; g_weight[t * 2 + 1] = w1;
        atomicAdd(&g_counts[e0], 1);
        atomicAdd(&g_counts[e1], 1);
    }
}

// ---------------- 2: exclusive scan over 8 counts ----------------
__global__ void scan_k() {
    if (threadIdx.x == 0) {
        int s = 0;
#pragma unroll
        for (int e = 0; e < E_NUM; e++) { g_offsets[e] = s; s += g_counts[e]; }
        g_offsets[E_NUM] = s;
    }
}

// ---------------- 3: dispatch assignment ----------------
__global__ void assign_k() {
    int i = blockIdx.x * blockDim.x + threadIdx.x;
    if (i >= NCOPIES) return;
    int e = g_expert[i];
    int p = g_offsets[e] + atomicAdd(&g_cursor[e], 1);
    g_pos[i] = p;
    g_row2tok[p] = i >> 1;   // token id
}

// ---------------- grouped GEMM tiles ----------------
#define BM 128
#define BN 64
#define BK 16
#define BMP (BM + 4)

// GEMM1: inter[row, :M] = silu(x_g @ wi0[e]) * (x_g @ wi1[e]); A rows gathered
__global__ void __launch_bounds__(256) gemm1_k(const float* __restrict__ x,
                                               const float* __restrict__ wi0,
                                               const float* __restrict__ wi1) {
    int e = blockIdx.z;
    int base = g_offsets[e];
    int cnt  = g_offsets[e + 1] - base;
    int row0 = blockIdx.y * BM;
    if (row0 >= cnt) return;
    int col0 = blockIdx.x * BN;

    __shared__ __align__(16) float As[BK][BMP];
    __shared__ __align__(16) float Bs0[BK][BN];
    __shared__ __align__(16) float Bs1[BK][BN];
    __shared__ int toks[BM];

    int tx = threadIdx.x;
    if (tx < BM) {
        int r = row0 + tx;
        toks[tx] = (r < cnt) ? g_row2tok[base + r] : g_row2tok[base];
    }
    __syncthreads();

    const float* B0 = wi0 + (size_t)e * D_DIM * M_DIM;
    const float* B1 = wi1 + (size_t)e * D_DIM * M_DIM;

    int tr = (tx >> 4) * 8;    // row offset of this thread's 8x4 tile
    int tc = (tx & 15) * 4;    // col offset

    unsigned long long acc0[8][2], acc1[8][2];
#pragma unroll
    for (int i = 0; i < 8; i++) {
        acc0[i][0] = acc0[i][1] = 0ull;
        acc1[i][0] = acc1[i][1] = 0ull;
    }

    int arow[2], ach[2];
#pragma unroll
    for (int i = 0; i < 2; i++) { int idx = tx + i * 256; arow[i] = idx >> 2; ach[i] = idx & 3; }
    int bkr = tx >> 4, bch = (tx & 15) * 4;

    for (int k0 = 0; k0 < D_DIM; k0 += BK) {
#pragma unroll
        for (int i = 0; i < 2; i++) {
            const float4 v = *reinterpret_cast<const float4*>(
                x + (size_t)toks[arow[i]] * D_DIM + k0 + ach[i] * 4);
            As[ach[i] * 4 + 0][arow[i]] = v.x;
            As[ach[i] * 4 + 1][arow[i]] = v.y;
            As[ach[i] * 4 + 2][arow[i]] = v.z;
            As[ach[i] * 4 + 3][arow[i]] = v.w;
        }
        *reinterpret_cast<float4*>(&Bs0[bkr][bch]) =
            *reinterpret_cast<const float4*>(B0 + (size_t)(k0 + bkr) * M_DIM + col0 + bch);
        *reinterpret_cast<float4*>(&Bs1[bkr][bch]) =
            *reinterpret_cast<const float4*>(B1 + (size_t)(k0 + bkr) * M_DIM + col0 + bch);
        __syncthreads();

#pragma unroll
        for (int kk = 0; kk < BK; kk++) {
            float4 aa = *reinterpret_cast<float4*>(&As[kk][tr]);
            float4 ab = *reinterpret_cast<float4*>(&As[kk][tr + 4]);
            float av[8] = {aa.x, aa.y, aa.z, aa.w, ab.x, ab.y, ab.z, ab.w};
            ulonglong2 b0 = *reinterpret_cast<ulonglong2*>(&Bs0[kk][tc]);
            ulonglong2 b1 = *reinterpret_cast<ulonglong2*>(&Bs1[kk][tc]);
#pragma unroll
            for (int i = 0; i < 8; i++) {
                unsigned long long a2 = pack2(av[i], av[i]);
                fma2(acc0[i][0], a2, b0.x);
                fma2(acc0[i][1], a2, b0.y);
                fma2(acc1[i][0], a2, b1.x);
                fma2(acc1[i][1], a2, b1.y);
            }
        }
        __syncthreads();
    }

#pragma unroll
    for (int i = 0; i < 8; i++) {
        int r = row0 + tr + i;
        if (r < cnt) {
            float h0[4], h1[4];
            unpack2(h0[0], h0[1], acc0[i][0]); unpack2(h0[2], h0[3], acc0[i][1]);
            unpack2(h1[0], h1[1], acc1[i][0]); unpack2(h1[2], h1[3], acc1[i][1]);
            float4 o;
            o.x = h0[0] / (1.f + expf(-h0[0])) * h1[0];
            o.y = h0[1] / (1.f + expf(-h0[1])) * h1[1];
            o.z = h0[2] / (1.f + expf(-h0[2])) * h1[2];
            o.w = h0[3] / (1.f + expf(-h0[3])) * h1[3];
            *reinterpret_cast<float4*>(&g_inter[(size_t)(base + r) * M_DIM + col0 + tc]) = o;
        }
    }
}

// GEMM2: out_sorted[row, :D] = inter[row, :M] @ wo[e]
__global__ void __launch_bounds__(256) gemm2_k(const float* __restrict__ wo) {
    int e = blockIdx.z;
    int base = g_offsets[e];
    int cnt  = g_offsets[e + 1] - base;
    int row0 = blockIdx.y * BM;
    if (row0 >= cnt) return;
    int col0 = blockIdx.x * BN;

    __shared__ __align__(16) float As[BK][BMP];
    __shared__ __align__(16) float Bs[BK][BN];
    __shared__ int rowsrc[BM];

    int tx = threadIdx.x;
    if (tx < BM) {
        int r = row0 + tx;
        rowsrc[tx] = base + (r < cnt ? r : cnt - 1);
    }
    __syncthreads();

    const float* B = wo + (size_t)e * M_DIM * D_DIM;

    int tr = (tx >> 4) * 8;
    int tc = (tx & 15) * 4;

    unsigned long long acc[8][2];
#pragma unroll
    for (int i = 0; i < 8; i++) acc[i][0] = acc[i][1] = 0ull;

    int arow[2], ach[2];
#pragma unroll
    for (int i = 0; i < 2; i++) { int idx = tx + i * 256; arow[i] = idx >> 2; ach[i] = idx & 3; }
    int bkr = tx >> 4, bch = (tx & 15) * 4;

    for (int k0 = 0; k0 < M_DIM; k0 += BK) {
#pragma unroll
        for (int i = 0; i < 2; i++) {
            const float4 v = *reinterpret_cast<const float4*>(
                g_inter + (size_t)rowsrc[arow[i]] * M_DIM + k0 + ach[i] * 4);
            As[ach[i] * 4 + 0][arow[i]] = v.x;
            As[ach[i] * 4 + 1][arow[i]] = v.y;
            As[ach[i] * 4 + 2][arow[i]] = v.z;
            As[ach[i] * 4 + 3][arow[i]] = v.w;
        }
        *reinterpret_cast<float4*>(&Bs[bkr][bch]) =
            *reinterpret_cast<const float4*>(B + (size_t)(k0 + bkr) * D_DIM + col0 + bch);
        __syncthreads();

#pragma unroll
        for (int kk = 0; kk < BK; kk++) {
            float4 aa = *reinterpret_cast<float4*>(&As[kk][tr]);
            float4 ab = *reinterpret_cast<float4*>(&As[kk][tr + 4]);
            float av[8] = {aa.x, aa.y, aa.z, aa.w, ab.x, ab.y, ab.z, ab.w};
            ulonglong2 b = *reinterpret_cast<ulonglong2*>(&Bs[kk][tc]);
#pragma unroll
            for (int i = 0; i < 8; i++) {
                unsigned long long a2 = pack2(av[i], av[i]);
                fma2(acc[i][0], a2, b.x);
                fma2(acc[i][1], a2, b.y);
            }
        }
        __syncthreads();
    }

#pragma unroll
    for (int i = 0; i < 8; i++) {
        int r = row0 + tr + i;
        if (r < cnt) {
            float c[4];
            unpack2(c[0], c[1], acc[i][0]); unpack2(c[2], c[3], acc[i][1]);
            float4 o = {c[0], c[1], c[2], c[3]};
            *reinterpret_cast<float4*>(&g_outsorted[(size_t)(base + r) * D_DIM + col0 + tc]) = o;
        }
    }
}

// ---------------- 6: weighted combine ----------------
__global__ void combine_k(float* __restrict__ out) {
    int t = blockIdx.x;
    float w0 = g_weight[t * 2 + 0];
    float w1 = g_weight[t * 2 + 1];
    const float* p0 = g_outsorted + (size_t)g_pos[t * 2 + 0] * D_DIM;
    const float* p1 = g_outsorted + (size_t)g_pos[t * 2 + 1] * D_DIM;
    float* o = out + (size_t)t * D_DIM;
    for (int d = threadIdx.x * 4; d < D_DIM; d += blockDim.x * 4) {
        float4 a = *reinterpret_cast<const float4*>(p0 + d);
        float4 b = *reinterpret_cast<const float4*>(p1 + d);
        float4 r;
        r.x = w0 * a.x + w1 * b.x;
        r.y = w0 * a.y + w1 * b.y;
        r.z = w0 * a.z + w1 * b.z;
        r.w = w0 * a.w + w1 * b.w;
        *reinterpret_cast<float4*>(o + d) = r;
    }
}

// ---------------- launch ----------------
extern "C" void kernel_launch(void* const* d_in, const int* in_sizes, int n_in,
                              void* d_out, int out_size) {
    const float* x   = (const float*)d_in[0];
    const float* wg  = (const float*)d_in[1];
    const float* wi0 = (const float*)d_in[2];
    const float* wi1 = (const float*)d_in[3];
    const float* wo  = (const float*)d_in[4];
    float* out = (float*)d_out;

    init_k<<<1, 32>>>();
    router_k<<<T_TOK / 8, 256>>>(x, wg);
    scan_k<<<1, 32>>>();
    assign_k<<<NCOPIES / 256, 256>>>();

    dim3 g1(M_DIM / BN, NCOPIES / BM, E_NUM);   // (16, 128, 8)
    gemm1_k<<<g1, 256>>>(x, wi0, wi1);

    dim3 g2(D_DIM / BN, NCOPIES / BM, E_NUM);   // (32, 128, 8)
    gemm2_k<<<g2, 256>>>(wo);

    combine_k<<<T_TOK, 256>>>(out);
}

// round 5
// speedup vs baseline: 1.6465x; 1.6465x over previous
#include <cuda_runtime.h>
#include <cuda_bf16.h>
#include <cstdint>
#include <math.h>

// ---------------- Problem dims (fixed) ----------------
#define T_TOK   8192
#define D_DIM   2048
#define M_DIM   1024
#define E_NUM   8
#define NCOPIES (T_TOK*2)

// ---------------- Scratch ----------------
__device__ int   g_counts[E_NUM];
__device__ int   g_offsets[E_NUM + 1];
__device__ int   g_cursor[E_NUM];
__device__ int   g_expert[NCOPIES];
__device__ float g_weight[NCOPIES];
__device__ int   g_pos[NCOPIES];
__device__ int   g_row2tok[NCOPIES];

__device__ __nv_bfloat16 g_ax_hi[(size_t)NCOPIES * D_DIM];
__device__ __nv_bfloat16 g_ax_lo[(size_t)NCOPIES * D_DIM];
__device__ __nv_bfloat16 g_w1_hi[(size_t)E_NUM * 2 * M_DIM * D_DIM];  // [E][N=2048 interleaved][K=2048]
__device__ __nv_bfloat16 g_w1_lo[(size_t)E_NUM * 2 * M_DIM * D_DIM];
__device__ __nv_bfloat16 g_w2_hi[(size_t)E_NUM * D_DIM * M_DIM];      // [E][N=2048][K=1024]
__device__ __nv_bfloat16 g_w2_lo[(size_t)E_NUM * D_DIM * M_DIM];
__device__ __nv_bfloat16 g_inter_hi[(size_t)NCOPIES * M_DIM];
__device__ __nv_bfloat16 g_inter_lo[(size_t)NCOPIES * M_DIM];
__device__ float g_outsorted[(size_t)NCOPIES * D_DIM];

// ---------------- helpers ----------------
__device__ __forceinline__ uint32_t smem_u32(const void* p) {
    uint32_t a;
    asm("{ .reg .u64 t; cvta.to.shared.u64 t, %1; cvt.u32.u64 %0, t; }" : "=r"(a) : "l"(p));
    return a;
}
__device__ __forceinline__ void cp_async16(uint32_t dst, const void* src) {
    asm volatile("cp.async.cg.shared.global [%0], [%1], 16;" :: "r"(dst), "l"(src) : "memory");
}
__device__ __forceinline__ void cp_commit() {
    asm volatile("cp.async.commit_group;" ::: "memory");
}
__device__ __forceinline__ void cp_wait1() {
    asm volatile("cp.async.wait_group 1;" ::: "memory");
}
__device__ __forceinline__ void ldm_x4(uint32_t& r0, uint32_t& r1, uint32_t& r2, uint32_t& r3, uint32_t addr) {
    asm volatile("ldmatrix.sync.aligned.m8n8.x4.shared.b16 {%0,%1,%2,%3}, [%4];"
                 : "=r"(r0), "=r"(r1), "=r"(r2), "=r"(r3) : "r"(addr));
}
__device__ __forceinline__ void mma_bf16(float* c, const uint32_t* a, uint32_t b0, uint32_t b1) {
    asm volatile(
        "mma.sync.aligned.m16n8k16.row.col.f32.bf16.bf16.f32 "
        "{%0,%1,%2,%3}, {%4,%5,%6,%7}, {%8,%9}, {%0,%1,%2,%3};"
        : "+f"(c[0]), "+f"(c[1]), "+f"(c[2]), "+f"(c[3])
        : "r"(a[0]), "r"(a[1]), "r"(a[2]), "r"(a[3]), "r"(b0), "r"(b1));
}
__device__ __forceinline__ uint32_t bfpair_hi(float v0, float v1) {
    __nv_bfloat162 p = __halves2bfloat162(__float2bfloat16(v0), __float2bfloat16(v1));
    return *reinterpret_cast<uint32_t*>(&p);
}
__device__ __forceinline__ uint32_t bfpair_lo(float v0, float v1) {
    float r0 = v0 - __bfloat162float(__float2bfloat16(v0));
    float r1 = v1 - __bfloat162float(__float2bfloat16(v1));
    __nv_bfloat162 p = __halves2bfloat162(__float2bfloat16(r0), __float2bfloat16(r1));
    return *reinterpret_cast<uint32_t*>(&p);
}

// ---------------- routing ----------------
__global__ void init_k() {
    int i = threadIdx.x;
    if (i < E_NUM) { g_counts[i] = 0; g_cursor[i] = 0; }
}

__global__ void router_k(const float* __restrict__ x, const float* __restrict__ wg) {
    int warp = threadIdx.x >> 5;
    int lane = threadIdx.x & 31;
    int t = blockIdx.x * 8 + warp;
    if (t >= T_TOK) return;
    const float* xr = x + (size_t)t * D_DIM;
    float acc[E_NUM];
    for (int e = 0; e < E_NUM; e++) acc[e] = 0.f;
    for (int d = lane; d < D_DIM; d += 32) {
        float xv = xr[d];
        const float* w = wg + (size_t)d * E_NUM;
        for (int e = 0; e < E_NUM; e++) acc[e] = fmaf(xv, w[e], acc[e]);
    }
    for (int e = 0; e < E_NUM; e++) {
        for (int o = 16; o > 0; o >>= 1) acc[e] += __shfl_xor_sync(0xffffffffu, acc[e], o);
    }
    if (lane == 0) {
        int e0 = 0; float l0 = acc[0];
        for (int e = 1; e < E_NUM; e++) { if (acc[e] > l0) { l0 = acc[e]; e0 = e; } }
        int e1 = -1; float l1 = -INFINITY;
        for (int e = 0; e < E_NUM; e++) { if (e != e0 && acc[e] > l1) { l1 = acc[e]; e1 = e; } }
        float w0 = 1.f / (1.f + expf(l1 - l0));
        g_expert[t * 2 + 0] = e0;
        g_expert[t * 2 + 1] = e1;
        g_weight[t * 2 + 0] = w0;
        g_weight[t * 2 + 1] = 1.f - w0;
        atomicAdd(&g_counts[e0], 1);
        atomicAdd(&g_counts[e1], 1);
    }
}

__global__ void scan_k() {
    if (threadIdx.x == 0) {
        int s = 0;
        for (int e = 0; e < E_NUM; e++) { g_offsets[e] = s; s += g_counts[e]; }
        g_offsets[E_NUM] = s;
    }
}

__global__ void assign_k() {
    int i = blockIdx.x * blockDim.x + threadIdx.x;
    if (i >= NCOPIES) return;
    int e = g_expert[i];
    int p = g_offsets[e] + atomicAdd(&g_cursor[e], 1);
    g_pos[i] = p;
    g_row2tok[p] = i >> 1;
}

// ---------------- conversions ----------------
__global__ void convx_k(const float* __restrict__ x) {
    int p = blockIdx.x;
    int tok = g_row2tok[p];
    const float4* src = reinterpret_cast<const float4*>(x + (size_t)tok * D_DIM);
    int t = threadIdx.x;
    float4 a = src[t * 2];
    float4 b = src[t * 2 + 1];
    float v[8];
    v[0] = a.x; v[1] = a.y; v[2] = a.z; v[3] = a.w;
    v[4] = b.x; v[5] = b.y; v[6] = b.z; v[7] = b.w;
    uint4 ph, pl;
    ph.x = bfpair_hi(v[0], v[1]); pl.x = bfpair_lo(v[0], v[1]);
    ph.y = bfpair_hi(v[2], v[3]); pl.y = bfpair_lo(v[2], v[3]);
    ph.z = bfpair_hi(v[4], v[5]); pl.z = bfpair_lo(v[4], v[5]);
    ph.w = bfpair_hi(v[6], v[7]); pl.w = bfpair_lo(v[6], v[7]);
    size_t ob = (size_t)p * D_DIM + (size_t)t * 8;
    *reinterpret_cast<uint4*>(g_ax_hi + ob) = ph;
    *reinterpret_cast<uint4*>(g_ax_lo + ob) = pl;
}

__global__ void convw1_k(const float* __restrict__ wi0, const float* __restrict__ wi1) {
    __shared__ float tile[32][33];
    int z = blockIdx.z;
    int e = z >> 1;
    int s = z & 1;
    int d0 = blockIdx.x * 32;
    int m0 = blockIdx.y * 32;
    int tx = threadIdx.x;
    int ty = threadIdx.y;
    const float* src = (s ? wi1 : wi0) + (size_t)e * D_DIM * M_DIM;
    for (int r = 0; r < 4; r++) {
        tile[ty + 8 * r][tx] = src[(size_t)(d0 + ty + 8 * r) * M_DIM + m0 + tx];
    }
    __syncthreads();
    for (int r = 0; r < 4; r++) {
        int mloc = ty + 8 * r;
        int n = 2 * (m0 + mloc) + s;
        float v = tile[tx][mloc];
        __nv_bfloat16 h = __float2bfloat16(v);
        size_t o = ((size_t)e * 2048 + (size_t)n) * D_DIM + d0 + tx;
        g_w1_hi[o] = h;
        g_w1_lo[o] = __float2bfloat16(v - __bfloat162float(h));
    }
}

__global__ void convw2_k(const float* __restrict__ wo) {
    __shared__ float tile[32][33];
    int e = blockIdx.z;
    int m0 = blockIdx.x * 32;
    int d0 = blockIdx.y * 32;
    int tx = threadIdx.x;
    int ty = threadIdx.y;
    const float* src = wo + (size_t)e * M_DIM * D_DIM;
    for (int r = 0; r < 4; r++) {
        tile[ty + 8 * r][tx] = src[(size_t)(m0 + ty + 8 * r) * D_DIM + d0 + tx];
    }
    __syncthreads();
    for (int r = 0; r < 4; r++) {
        int n = d0 + ty + 8 * r;
        float v = tile[tx][ty + 8 * r];
        __nv_bfloat16 h = __float2bfloat16(v);
        size_t o = ((size_t)e * D_DIM + (size_t)n) * M_DIM + m0 + tx;
        g_w2_hi[o] = h;
        g_w2_lo[o] = __float2bfloat16(v - __bfloat162float(h));
    }
}

// ---------------- mma.sync grouped GEMM ----------------
// CTA tile 128(M) x 128(N), BK=32, 8 warps (2x4), warp tile 64x32.
// Smem rows padded to 80B (40 bf16) -> conflict-free ldmatrix.
// 3-term split: Ah*Bh + Ah*Bl + Al*Bh.
#define ROWB      80
#define A_BYTES   (128*ROWB)     // 10240
#define STG_BYTES (4*A_BYTES)    // Ah,Al,Bh,Bl = 40960
#define NSTAGE    3
#define SMEM_REQ  (NSTAGE*STG_BYTES)

// Issues one stage of cp.async loads (8x16B per thread).
__device__ __forceinline__ void load_stage(
    uint32_t sbase, int stg, int tx,
    const __nv_bfloat16* Ah, const __nv_bfloat16* Al,
    const __nv_bfloat16* Bh, const __nv_bfloat16* Bl,
    int aRowBase, int cnt, size_t bRowBase, int KT, int k0)
{
    uint32_t s0 = sbase + (uint32_t)stg * STG_BYTES;
    for (int i = 0; i < 2; i++) {
        int id = tx + i * 256;
        int row = id >> 2;
        int cc = id & 3;
        int rr = row;
        if (rr > cnt - 1 - 0) {}
        int rclamp = (row < cnt) ? row : (cnt - 1);
        size_t goA = (size_t)(aRowBase + rclamp) * KT + k0 + cc * 8;
        uint32_t off = (uint32_t)(row * ROWB + cc * 16);
        cp_async16(s0 + off, Ah + goA);
        cp_async16(s0 + A_BYTES + off, Al + goA);
        size_t goB = (bRowBase + (size_t)row) * KT + k0 + cc * 8;
        cp_async16(s0 + 2 * A_BYTES + off, Bh + goB);
        cp_async16(s0 + 3 * A_BYTES + off, Bl + goB);
    }
}

// Core mainloop: accumulates acc[4][4][4].
__device__ __forceinline__ void gemm_mainloop(
    uint32_t sbase, int tx,
    const __nv_bfloat16* Ah, const __nv_bfloat16* Al,
    const __nv_bfloat16* Bh, const __nv_bfloat16* Bl,
    int aRowBase, int cnt, size_t bRowBase, int KT,
    float acc[4][4][4])
{
    const int NITER = KT / 32;
    int wid = tx >> 5;
    int lane = tx & 31;
    int wm = wid >> 2;
    int wn = wid & 3;
    int l15 = lane & 15;
    int l16 = lane >> 4;

    // ldmatrix base offsets (within a stage)
    uint32_t aoff = (uint32_t)((wm * 64 + l15) * ROWB + l16 * 16);
    uint32_t boff = (uint32_t)(2 * A_BYTES + (wn * 32 + l15) * ROWB + l16 * 16);

    load_stage(sbase, 0, tx, Ah, Al, Bh, Bl, aRowBase, cnt, bRowBase, KT, 0);
    cp_commit();
    load_stage(sbase, 1, tx, Ah, Al, Bh, Bl, aRowBase, cnt, bRowBase, KT, 32);
    cp_commit();

    for (int it = 0; it < NITER; it++) {
        cp_wait1();
        __syncthreads();
        if (it + 2 < NITER) {
            load_stage(sbase, (it + 2) % NSTAGE, tx, Ah, Al, Bh, Bl,
                       aRowBase, cnt, bRowBase, KT, (it + 2) * 32);
        }
        cp_commit();

        uint32_t s0 = sbase + (uint32_t)(it % NSTAGE) * STG_BYTES;
        for (int kk = 0; kk < 2; kk++) {
            uint32_t ah[4][4], al[4][4], bh[2][4], bl[2][4];
            for (int mt = 0; mt < 4; mt++) {
                uint32_t ad = s0 + aoff + (uint32_t)(mt * 16 * ROWB + kk * 32);
                ldm_x4(ah[mt][0], ah[mt][1], ah[mt][2], ah[mt][3], ad);
                ldm_x4(al[mt][0], al[mt][1], al[mt][2], al[mt][3], ad + A_BYTES);
            }
            for (int g = 0; g < 2; g++) {
                uint32_t bd = s0 + boff + (uint32_t)(g * 16 * ROWB + kk * 32);
                ldm_x4(bh[g][0], bh[g][1], bh[g][2], bh[g][3], bd);
                ldm_x4(bl[g][0], bl[g][1], bl[g][2], bl[g][3], bd + A_BYTES);
            }
            for (int mt = 0; mt < 4; mt++) {
                for (int nt = 0; nt < 4; nt++) {
                    int g = nt >> 1;
                    int p = nt & 1;
                    uint32_t bh0 = bh[g][p], bh1 = bh[g][p + 2];
                    uint32_t bl0 = bl[g][p], bl1 = bl[g][p + 2];
                    mma_bf16(acc[mt][nt], ah[mt], bh0, bh1);
                    mma_bf16(acc[mt][nt], ah[mt], bl0, bl1);
                    mma_bf16(acc[mt][nt], al[mt], bh0, bh1);
                }
            }
        }
        __syncthreads();
    }
}

// GEMM1: K=2048, N=2048 interleaved, fused silu epilogue -> g_inter hi/lo
__global__ void __launch_bounds__(256, 1) gemm1_mma() {
    int e = blockIdx.z;
    int base = g_offsets[e];
    int cnt  = g_offsets[e + 1] - base;
    int row0 = blockIdx.y * 128;
    if (row0 >= cnt) return;
    int col0 = blockIdx.x * 128;

    extern __shared__ char smraw[];
    uint32_t sbase = smem_u32(smraw);
    int tx = threadIdx.x;

    float acc[4][4][4];
    for (int a = 0; a < 4; a++)
        for (int b = 0; b < 4; b++)
            for (int c = 0; c < 4; c++) acc[a][b][c] = 0.f;

    size_t bRowBase = (size_t)e * 2048 + col0;
    gemm_mainloop(sbase, tx, g_ax_hi, g_ax_lo, g_w1_hi, g_w1_lo,
                  base + row0, cnt - row0, bRowBase, 2048, acc);

    int wid = tx >> 5;
    int lane = tx & 31;
    int wm = wid >> 2;
    int wn = wid & 3;
    int qrow = lane >> 2;
    int qcol = lane & 3;
    for (int mt = 0; mt < 4; mt++) {
        for (int nt = 0; nt < 4; nt++) {
            int r0 = row0 + wm * 64 + mt * 16 + qrow;
            int icol = ((col0 + wn * 32 + nt * 8) >> 1) + qcol;
            float* c = acc[mt][nt];
            if (r0 < cnt) {
                float v = c[0] / (1.f + __expf(-c[0])) * c[1];
                __nv_bfloat16 h = __float2bfloat16(v);
                size_t o = (size_t)(base + r0) * M_DIM + icol;
                g_inter_hi[o] = h;
                g_inter_lo[o] = __float2bfloat16(v - __bfloat162float(h));
            }
            int r1 = r0 + 8;
            if (r1 < cnt) {
                float v = c[2] / (1.f + __expf(-c[2])) * c[3];
                __nv_bfloat16 h = __float2bfloat16(v);
                size_t o = (size_t)(base + r1) * M_DIM + icol;
                g_inter_hi[o] = h;
                g_inter_lo[o] = __float2bfloat16(v - __bfloat162float(h));
            }
        }
    }
}

// GEMM2: K=1024, N=2048, fp32 epilogue -> g_outsorted
__global__ void __launch_bounds__(256, 1) gemm2_mma() {
    int e = blockIdx.z;
    int base = g_offsets[e];
    int cnt  = g_offsets[e + 1] - base;
    int row0 = blockIdx.y * 128;
    if (row0 >= cnt) return;
    int col0 = blockIdx.x * 128;

    extern __shared__ char smraw[];
    uint32_t sbase = smem_u32(smraw);
    int tx = threadIdx.x;

    float acc[4][4][4];
    for (int a = 0; a < 4; a++)
        for (int b = 0; b < 4; b++)
            for (int c = 0; c < 4; c++) acc[a][b][c] = 0.f;

    size_t bRowBase = (size_t)e * 2048 + col0;
    gemm_mainloop(sbase, tx, g_inter_hi, g_inter_lo, g_w2_hi, g_w2_lo,
                  base + row0, cnt - row0, bRowBase, 1024, acc);

    int wid = tx >> 5;
    int lane = tx & 31;
    int wm = wid >> 2;
    int wn = wid & 3;
    int qrow = lane >> 2;
    int qcol = lane & 3;
    for (int mt = 0; mt < 4; mt++) {
        for (int nt = 0; nt < 4; nt++) {
            int r0 = row0 + wm * 64 + mt * 16 + qrow;
            int colg = col0 + wn * 32 + nt * 8 + qcol * 2;
            float* c = acc[mt][nt];
            if (r0 < cnt) {
                float2 v; v.x = c[0]; v.y = c[1];
                *reinterpret_cast<float2*>(g_outsorted + (size_t)(base + r0) * D_DIM + colg) = v;
            }
            int r1 = r0 + 8;
            if (r1 < cnt) {
                float2 v; v.x = c[2]; v.y = c[3];
                *reinterpret_cast<float2*>(g_outsorted + (size_t)(base + r1) * D_DIM + colg) = v;
            }
        }
    }
}

// ---------------- combine ----------------
__global__ void combine_k(float* __restrict__ out) {
    int t = blockIdx.x;
    float w0 = g_weight[t * 2 + 0];
    float w1 = g_weight[t * 2 + 1];
    const float* p0 = g_outsorted + (size_t)g_pos[t * 2 + 0] * D_DIM;
    const float* p1 = g_outsorted + (size_t)g_pos[t * 2 + 1] * D_DIM;
    float* o = out + (size_t)t * D_DIM;
    for (int d = threadIdx.x * 4; d < D_DIM; d += blockDim.x * 4) {
        float4 a = *reinterpret_cast<const float4*>(p0 + d);
        float4 b = *reinterpret_cast<const float4*>(p1 + d);
        float4 r;
        r.x = w0 * a.x + w1 * b.x;
        r.y = w0 * a.y + w1 * b.y;
        r.z = w0 * a.z + w1 * b.z;
        r.w = w0 * a.w + w1 * b.w;
        *reinterpret_cast<float4*>(o + d) = r;
    }
}

// ---------------- launch ----------------
extern "C" void kernel_launch(void* const* d_in, const int* in_sizes, int n_in,
                              void* d_out, int out_size) {
    const float* x   = (const float*)d_in[0];
    const float* wg  = (const float*)d_in[1];
    const float* wi0 = (const float*)d_in[2];
    const float* wi1 = (const float*)d_in[3];
    const float* wo  = (const float*)d_in[4];
    float* out = (float*)d_out;

    cudaFuncSetAttribute(gemm1_mma, cudaFuncAttributeMaxDynamicSharedMemorySize, SMEM_REQ);
    cudaFuncSetAttribute(gemm2_mma, cudaFuncAttributeMaxDynamicSharedMemorySize, SMEM_REQ);

    init_k<<<1, 32>>>();
    router_k<<<T_TOK / 8, 256>>>(x, wg);
    scan_k<<<1, 32>>>();
    assign_k<<<NCOPIES / 256, 256>>>();

    convx_k<<<NCOPIES, 256>>>(x);
    convw1_k<<<dim3(D_DIM / 32, M_DIM / 32, E_NUM * 2), dim3(32, 8)>>>(wi0, wi1);
    convw2_k<<<dim3(M_DIM / 32, D_DIM / 32, E_NUM), dim3(32, 8)>>>(wo);

    dim3 g1(2 * M_DIM / 128, NCOPIES / 128, E_NUM);   // (16, 128, 8)
    gemm1_mma<<<g1, 256, SMEM_REQ>>>();

    dim3 g2(D_DIM / 128, NCOPIES / 128, E_NUM);       // (16, 128, 8)
    gemm2_mma<<<g2, 256, SMEM_REQ>>>();

    combine_k<<<T_TOK, 256>>>(out);
}

// round 6
// speedup vs baseline: 2.5485x; 1.5478x over previous
#include <cuda_runtime.h>
#include <cuda_fp16.h>
#include <cstdint>
#include <math.h>

// ---------------- Problem dims (fixed) ----------------
#define T_TOK   8192
#define D_DIM   2048
#define M_DIM   1024
#define E_NUM   8
#define NCOPIES (T_TOK*2)

// ---------------- Scratch ----------------
__device__ int   g_counts[E_NUM];
__device__ int   g_offsets[E_NUM + 1];
__device__ int   g_cursor[E_NUM];
__device__ int   g_expert[NCOPIES];
__device__ float g_weight[NCOPIES];
__device__ int   g_pos[NCOPIES];
__device__ int   g_row2tok[NCOPIES];

__device__ __half g_ax_hi[(size_t)NCOPIES * D_DIM];
__device__ __half g_ax_lo[(size_t)NCOPIES * D_DIM];
__device__ __half g_w1[(size_t)E_NUM * 2 * M_DIM * D_DIM];   // [E][N=2048 interleaved][K=2048]
__device__ __half g_w2[(size_t)E_NUM * D_DIM * M_DIM];       // [E][N=2048][K=1024]
__device__ __half g_inter_hi[(size_t)NCOPIES * M_DIM];
__device__ __half g_inter_lo[(size_t)NCOPIES * M_DIM];
__device__ float g_outsorted[(size_t)NCOPIES * D_DIM];

// ---------------- helpers ----------------
__device__ __forceinline__ uint32_t smem_u32(const void* p) {
    uint32_t a;
    asm("{ .reg .u64 t; cvta.to.shared.u64 t, %1; cvt.u32.u64 %0, t; }" : "=r"(a) : "l"(p));
    return a;
}
__device__ __forceinline__ void cp_async16(uint32_t dst, const void* src) {
    asm volatile("cp.async.cg.shared.global [%0], [%1], 16;" :: "r"(dst), "l"(src) : "memory");
}
__device__ __forceinline__ void cp_commit() {
    asm volatile("cp.async.commit_group;" ::: "memory");
}
__device__ __forceinline__ void cp_wait1() {
    asm volatile("cp.async.wait_group 1;" ::: "memory");
}
__device__ __forceinline__ void ldm_x4(uint32_t& r0, uint32_t& r1, uint32_t& r2, uint32_t& r3, uint32_t addr) {
    asm volatile("ldmatrix.sync.aligned.m8n8.x4.shared.b16 {%0,%1,%2,%3}, [%4];"
                 : "=r"(r0), "=r"(r1), "=r"(r2), "=r"(r3) : "r"(addr));
}
__device__ __forceinline__ void mma_f16(float* c, const uint32_t* a, uint32_t b0, uint32_t b1) {
    asm volatile(
        "mma.sync.aligned.m16n8k16.row.col.f32.f16.f16.f32 "
        "{%0,%1,%2,%3}, {%4,%5,%6,%7}, {%8,%9}, {%0,%1,%2,%3};"
        : "+f"(c[0]), "+f"(c[1]), "+f"(c[2]), "+f"(c[3])
        : "r"(a[0]), "r"(a[1]), "r"(a[2]), "r"(a[3]), "r"(b0), "r"(b1));
}

// ---------------- routing ----------------
__global__ void init_k() {
    int i = threadIdx.x;
    if (i < E_NUM) { g_counts[i] = 0; g_cursor[i] = 0; }
}

__global__ void router_k(const float* __restrict__ x, const float* __restrict__ wg) {
    int warp = threadIdx.x >> 5;
    int lane = threadIdx.x & 31;
    int t = blockIdx.x * 8 + warp;
    if (t >= T_TOK) return;
    const float* xr = x + (size_t)t * D_DIM;
    float acc[E_NUM];
    for (int e = 0; e < E_NUM; e++) acc[e] = 0.f;
    for (int d = lane; d < D_DIM; d += 32) {
        float xv = xr[d];
        const float* w = wg + (size_t)d * E_NUM;
        for (int e = 0; e < E_NUM; e++) acc[e] = fmaf(xv, w[e], acc[e]);
    }
    for (int e = 0; e < E_NUM; e++) {
        for (int o = 16; o > 0; o >>= 1) acc[e] += __shfl_xor_sync(0xffffffffu, acc[e], o);
    }
    if (lane == 0) {
        int e0 = 0; float l0 = acc[0];
        for (int e = 1; e < E_NUM; e++) { if (acc[e] > l0) { l0 = acc[e]; e0 = e; } }
        int e1 = -1; float l1 = -INFINITY;
        for (int e = 0; e < E_NUM; e++) { if (e != e0 && acc[e] > l1) { l1 = acc[e]; e1 = e; } }
        float w0 = 1.f / (1.f + expf(l1 - l0));
        g_expert[t * 2 + 0] = e0;
        g_expert[t * 2 + 1] = e1;
        g_weight[t * 2 + 0] = w0;
        g_weight[t * 2 + 1] = 1.f - w0;
        atomicAdd(&g_counts[e0], 1);
        atomicAdd(&g_counts[e1], 1);
    }
}

__global__ void scan_k() {
    if (threadIdx.x == 0) {
        int s = 0;
        for (int e = 0; e < E_NUM; e++) { g_offsets[e] = s; s += g_counts[e]; }
        g_offsets[E_NUM] = s;
    }
}

__global__ void assign_k() {
    int i = blockIdx.x * blockDim.x + threadIdx.x;
    if (i >= NCOPIES) return;
    int e = g_expert[i];
    int p = g_offsets[e] + atomicAdd(&g_cursor[e], 1);
    g_pos[i] = p;
    g_row2tok[p] = i >> 1;
}

// ---------------- conversions ----------------
__global__ void convx_k(const float* __restrict__ x) {
    int p = blockIdx.x;
    int tok = g_row2tok[p];
    const float4* src = reinterpret_cast<const float4*>(x + (size_t)tok * D_DIM);
    int t = threadIdx.x;
    float4 a = src[t * 2];
    float4 b = src[t * 2 + 1];
    float v[8];
    v[0] = a.x; v[1] = a.y; v[2] = a.z; v[3] = a.w;
    v[4] = b.x; v[5] = b.y; v[6] = b.z; v[7] = b.w;
    __half hh[8], hl[8];
    for (int i = 0; i < 8; i++) {
        hh[i] = __float2half(v[i]);
        hl[i] = __float2half(v[i] - __half2float(hh[i]));
    }
    size_t ob = (size_t)p * D_DIM + (size_t)t * 8;
    *reinterpret_cast<uint4*>(g_ax_hi + ob) = *reinterpret_cast<uint4*>(hh);
    *reinterpret_cast<uint4*>(g_ax_lo + ob) = *reinterpret_cast<uint4*>(hl);
}

__global__ void convw1_k(const float* __restrict__ wi0, const float* __restrict__ wi1) {
    __shared__ float tile[32][33];
    int z = blockIdx.z;
    int e = z >> 1;
    int s = z & 1;
    int d0 = blockIdx.x * 32;
    int m0 = blockIdx.y * 32;
    int tx = threadIdx.x;
    int ty = threadIdx.y;
    const float* src = (s ? wi1 : wi0) + (size_t)e * D_DIM * M_DIM;
    for (int r = 0; r < 4; r++) {
        tile[ty + 8 * r][tx] = src[(size_t)(d0 + ty + 8 * r) * M_DIM + m0 + tx];
    }
    __syncthreads();
    for (int r = 0; r < 4; r++) {
        int mloc = ty + 8 * r;
        int n = 2 * (m0 + mloc) + s;
        float v = tile[tx][mloc];
        size_t o = ((size_t)e * 2048 + (size_t)n) * D_DIM + d0 + tx;
        g_w1[o] = __float2half(v);
    }
}

__global__ void convw2_k(const float* __restrict__ wo) {
    __shared__ float tile[32][33];
    int e = blockIdx.z;
    int m0 = blockIdx.x * 32;
    int d0 = blockIdx.y * 32;
    int tx = threadIdx.x;
    int ty = threadIdx.y;
    const float* src = wo + (size_t)e * M_DIM * D_DIM;
    for (int r = 0; r < 4; r++) {
        tile[ty + 8 * r][tx] = src[(size_t)(m0 + ty + 8 * r) * D_DIM + d0 + tx];
    }
    __syncthreads();
    for (int r = 0; r < 4; r++) {
        int n = d0 + ty + 8 * r;
        float v = tile[tx][ty + 8 * r];
        size_t o = ((size_t)e * D_DIM + (size_t)n) * M_DIM + m0 + tx;
        g_w2[o] = __float2half(v);
    }
}

// ---------------- mma.sync grouped GEMM ----------------
// CTA tile 128(M) x 128(N), BK=32, 8 warps (2x4), warp tile 64x32.
// Smem rows padded to 80B -> conflict-free ldmatrix.
// 2-term split: Ah*B + Al*B (A split fp16 hi/lo, B single fp16).
#define ROWB      80
#define A_BYTES   (128*ROWB)     // 10240
#define STG_BYTES (3*A_BYTES)    // Ah, Al, B = 30720
#define NSTAGE    3
#define SMEM_REQ  (NSTAGE*STG_BYTES)

__device__ __forceinline__ void load_stage(
    uint32_t sbase, int stg, int tx,
    const __half* Ah, const __half* Al, const __half* B,
    int aRowBase, int cnt, size_t bRowBase, int KT, int k0)
{
    uint32_t s0 = sbase + (uint32_t)stg * STG_BYTES;
    for (int i = 0; i < 2; i++) {
        int id = tx + i * 256;
        int row = id >> 2;
        int cc = id & 3;
        int rclamp = (row < cnt) ? row : (cnt - 1);
        size_t goA = (size_t)(aRowBase + rclamp) * KT + k0 + cc * 8;
        uint32_t off = (uint32_t)(row * ROWB + cc * 16);
        cp_async16(s0 + off, Ah + goA);
        cp_async16(s0 + A_BYTES + off, Al + goA);
        size_t goB = (bRowBase + (size_t)row) * KT + k0 + cc * 8;
        cp_async16(s0 + 2 * A_BYTES + off, B + goB);
    }
}

__device__ __forceinline__ void gemm_mainloop(
    uint32_t sbase, int tx,
    const __half* Ah, const __half* Al, const __half* B,
    int aRowBase, int cnt, size_t bRowBase, int KT,
    float acc[4][4][4])
{
    const int NITER = KT / 32;
    int wid = tx >> 5;
    int lane = tx & 31;
    int wm = wid >> 2;
    int wn = wid & 3;
    int l15 = lane & 15;
    int l16 = lane >> 4;

    uint32_t aoff = (uint32_t)((wm * 64 + l15) * ROWB + l16 * 16);
    uint32_t boff = (uint32_t)(2 * A_BYTES + (wn * 32 + l15) * ROWB + l16 * 16);

    load_stage(sbase, 0, tx, Ah, Al, B, aRowBase, cnt, bRowBase, KT, 0);
    cp_commit();
    load_stage(sbase, 1, tx, Ah, Al, B, aRowBase, cnt, bRowBase, KT, 32);
    cp_commit();

    for (int it = 0; it < NITER; it++) {
        cp_wait1();
        __syncthreads();
        if (it + 2 < NITER) {
            load_stage(sbase, (it + 2) % NSTAGE, tx, Ah, Al, B,
                       aRowBase, cnt, bRowBase, KT, (it + 2) * 32);
        }
        cp_commit();

        uint32_t s0 = sbase + (uint32_t)(it % NSTAGE) * STG_BYTES;
        for (int kk = 0; kk < 2; kk++) {
            uint32_t ah[4][4], al[4][4], bb[2][4];
            for (int mt = 0; mt < 4; mt++) {
                uint32_t ad = s0 + aoff + (uint32_t)(mt * 16 * ROWB + kk * 32);
                ldm_x4(ah[mt][0], ah[mt][1], ah[mt][2], ah[mt][3], ad);
                ldm_x4(al[mt][0], al[mt][1], al[mt][2], al[mt][3], ad + A_BYTES);
            }
            for (int g = 0; g < 2; g++) {
                uint32_t bd = s0 + boff + (uint32_t)(g * 16 * ROWB + kk * 32);
                ldm_x4(bb[g][0], bb[g][1], bb[g][2], bb[g][3], bd);
            }
            for (int mt = 0; mt < 4; mt++) {
                for (int nt = 0; nt < 4; nt++) {
                    int g = nt >> 1;
                    int p = nt & 1;
                    uint32_t b0 = bb[g][p];
                    uint32_t b1 = bb[g][p + 2];
                    mma_f16(acc[mt][nt], ah[mt], b0, b1);
                    mma_f16(acc[mt][nt], al[mt], b0, b1);
                }
            }
        }
        __syncthreads();
    }
}

// GEMM1: K=2048, N=2048 interleaved, fused silu epilogue -> g_inter hi/lo
__global__ void __launch_bounds__(256, 1) gemm1_mma() {
    int e = blockIdx.z;
    int base = g_offsets[e];
    int cnt  = g_offsets[e + 1] - base;
    int row0 = blockIdx.y * 128;
    if (row0 >= cnt) return;
    int col0 = blockIdx.x * 128;

    extern __shared__ char smraw[];
    uint32_t sbase = smem_u32(smraw);
    int tx = threadIdx.x;

    float acc[4][4][4];
    for (int a = 0; a < 4; a++)
        for (int b = 0; b < 4; b++)
            for (int c = 0; c < 4; c++) acc[a][b][c] = 0.f;

    size_t bRowBase = (size_t)e * 2048 + col0;
    gemm_mainloop(sbase, tx, g_ax_hi, g_ax_lo, g_w1,
                  base + row0, cnt - row0, bRowBase, 2048, acc);

    int wid = tx >> 5;
    int lane = tx & 31;
    int wm = wid >> 2;
    int wn = wid & 3;
    int qrow = lane >> 2;
    int qcol = lane & 3;
    for (int mt = 0; mt < 4; mt++) {
        for (int nt = 0; nt < 4; nt++) {
            int r0 = row0 + wm * 64 + mt * 16 + qrow;
            int icol = ((col0 + wn * 32 + nt * 8) >> 1) + qcol;
            float* c = acc[mt][nt];
            if (r0 < cnt) {
                float v = c[0] / (1.f + __expf(-c[0])) * c[1];
                __half h = __float2half(v);
                size_t o = (size_t)(base + r0) * M_DIM + icol;
                g_inter_hi[o] = h;
                g_inter_lo[o] = __float2half(v - __half2float(h));
            }
            int r1 = r0 + 8;
            if (r1 < cnt) {
                float v = c[2] / (1.f + __expf(-c[2])) * c[3];
                __half h = __float2half(v);
                size_t o = (size_t)(base + r1) * M_DIM + icol;
                g_inter_hi[o] = h;
                g_inter_lo[o] = __float2half(v - __half2float(h));
            }
        }
    }
}

// GEMM2: K=1024, N=2048, fp32 epilogue -> g_outsorted
__global__ void __launch_bounds__(256, 1) gemm2_mma() {
    int e = blockIdx.z;
    int base = g_offsets[e];
    int cnt  = g_offsets[e + 1] - base;
    int row0 = blockIdx.y * 128;
    if (row0 >= cnt) return;
    int col0 = blockIdx.x * 128;

    extern __shared__ char smraw[];
    uint32_t sbase = smem_u32(smraw);
    int tx = threadIdx.x;

    float acc[4][4][4];
    for (int a = 0; a < 4; a++)
        for (int b = 0; b < 4; b++)
            for (int c = 0; c < 4; c++) acc[a][b][c] = 0.f;

    size_t bRowBase = (size_t)e * 2048 + col0;
    gemm_mainloop(sbase, tx, g_inter_hi, g_inter_lo, g_w2,
                  base + row0, cnt - row0, bRowBase, 1024, acc);

    int wid = tx >> 5;
    int lane = tx & 31;
    int wm = wid >> 2;
    int wn = wid & 3;
    int qrow = lane >> 2;
    int qcol = lane & 3;
    for (int mt = 0; mt < 4; mt++) {
        for (int nt = 0; nt < 4; nt++) {
            int r0 = row0 + wm * 64 + mt * 16 + qrow;
            int colg = col0 + wn * 32 + nt * 8 + qcol * 2;
            float* c = acc[mt][nt];
            if (r0 < cnt) {
                float2 v; v.x = c[0]; v.y = c[1];
                *reinterpret_cast<float2*>(g_outsorted + (size_t)(base + r0) * D_DIM + colg) = v;
            }
            int r1 = r0 + 8;
            if (r1 < cnt) {
                float2 v; v.x = c[2]; v.y = c[3];
                *reinterpret_cast<float2*>(g_outsorted + (size_t)(base + r1) * D_DIM + colg) = v;
            }
        }
    }
}

// ---------------- combine ----------------
__global__ void combine_k(float* __restrict__ out) {
    int t = blockIdx.x;
    float w0 = g_weight[t * 2 + 0];
    float w1 = g_weight[t * 2 + 1];
    const float* p0 = g_outsorted + (size_t)g_pos[t * 2 + 0] * D_DIM;
    const float* p1 = g_outsorted + (size_t)g_pos[t * 2 + 1] * D_DIM;
    float* o = out + (size_t)t * D_DIM;
    for (int d = threadIdx.x * 4; d < D_DIM; d += blockDim.x * 4) {
        float4 a = *reinterpret_cast<const float4*>(p0 + d);
        float4 b = *reinterpret_cast<const float4*>(p1 + d);
        float4 r;
        r.x = w0 * a.x + w1 * b.x;
        r.y = w0 * a.y + w1 * b.y;
        r.z = w0 * a.z + w1 * b.z;
        r.w = w0 * a.w + w1 * b.w;
        *reinterpret_cast<float4*>(o + d) = r;
    }
}

// ---------------- launch ----------------
extern "C" void kernel_launch(void* const* d_in, const int* in_sizes, int n_in,
                              void* d_out, int out_size) {
    const float* x   = (const float*)d_in[0];
    const float* wg  = (const float*)d_in[1];
    const float* wi0 = (const float*)d_in[2];
    const float* wi1 = (const float*)d_in[3];
    const float* wo  = (const float*)d_in[4];
    float* out = (float*)d_out;

    cudaFuncSetAttribute(gemm1_mma, cudaFuncAttributeMaxDynamicSharedMemorySize, SMEM_REQ);
    cudaFuncSetAttribute(gemm2_mma, cudaFuncAttributeMaxDynamicSharedMemorySize, SMEM_REQ);

    init_k<<<1, 32>>>();
    router_k<<<T_TOK / 8, 256>>>(x, wg);
    scan_k<<<1, 32>>>();
    assign_k<<<NCOPIES / 256, 256>>>();

    convx_k<<<NCOPIES, 256>>>(x);
    convw1_k<<<dim3(D_DIM / 32, M_DIM / 32, E_NUM * 2), dim3(32, 8)>>>(wi0, wi1);
    convw2_k<<<dim3(M_DIM / 32, D_DIM / 32, E_NUM), dim3(32, 8)>>>(wo);

    dim3 g1(2 * M_DIM / 128, NCOPIES / 128, E_NUM);   // (16, 128, 8)
    gemm1_mma<<<g1, 256, SMEM_REQ>>>();

    dim3 g2(D_DIM / 128, NCOPIES / 128, E_NUM);       // (16, 128, 8)
    gemm2_mma<<<g2, 256, SMEM_REQ>>>();

    combine_k<<<T_TOK, 256>>>(out);
}

// round 7
// speedup vs baseline: 4.1275x; 1.6196x over previous
#include <cuda_runtime.h>
#include <cuda_fp16.h>
#include <cstdint>
#include <math.h>

// ---------------- Problem dims (fixed) ----------------
#define T_TOK   8192
#define D_DIM   2048
#define M_DIM   1024
#define E_NUM   8
#define NCOPIES (T_TOK*2)

// ---------------- Scratch ----------------
__device__ int   g_counts[E_NUM];
__device__ int   g_offsets[E_NUM + 1];
__device__ int   g_cursor[E_NUM];
__device__ int   g_expert[NCOPIES];
__device__ float g_weight[NCOPIES];
__device__ int   g_pos[NCOPIES];
__device__ int   g_row2tok[NCOPIES];

__device__ __half g_ax[(size_t)NCOPIES * D_DIM];
__device__ __half g_w1[(size_t)E_NUM * 2 * M_DIM * D_DIM];   // [E][N=2048 interleaved][K=2048]
__device__ __half g_w2[(size_t)E_NUM * D_DIM * M_DIM];       // [E][N=2048][K=1024]
__device__ __half g_inter[(size_t)NCOPIES * M_DIM];
__device__ float g_outsorted[(size_t)NCOPIES * D_DIM];

// ---------------- helpers ----------------
__device__ __forceinline__ uint32_t smem_u32(const void* p) {
    uint32_t a;
    asm("{ .reg .u64 t; cvta.to.shared.u64 t, %1; cvt.u32.u64 %0, t; }" : "=r"(a) : "l"(p));
    return a;
}
__device__ __forceinline__ void cp_async16(uint32_t dst, const void* src) {
    asm volatile("cp.async.cg.shared.global [%0], [%1], 16;" :: "r"(dst), "l"(src) : "memory");
}
__device__ __forceinline__ void cp_commit() {
    asm volatile("cp.async.commit_group;" ::: "memory");
}
__device__ __forceinline__ void cp_wait1() {
    asm volatile("cp.async.wait_group 1;" ::: "memory");
}
__device__ __forceinline__ void ldm_x4(uint32_t& r0, uint32_t& r1, uint32_t& r2, uint32_t& r3, uint32_t addr) {
    asm volatile("ldmatrix.sync.aligned.m8n8.x4.shared.b16 {%0,%1,%2,%3}, [%4];"
                 : "=r"(r0), "=r"(r1), "=r"(r2), "=r"(r3) : "r"(addr));
}
__device__ __forceinline__ void mma_f16(float* c, const uint32_t* a, uint32_t b0, uint32_t b1) {
    asm volatile(
        "mma.sync.aligned.m16n8k16.row.col.f32.f16.f16.f32 "
        "{%0,%1,%2,%3}, {%4,%5,%6,%7}, {%8,%9}, {%0,%1,%2,%3};"
        : "+f"(c[0]), "+f"(c[1]), "+f"(c[2]), "+f"(c[3])
        : "r"(a[0]), "r"(a[1]), "r"(a[2]), "r"(a[3]), "r"(b0), "r"(b1));
}

// ---------------- routing ----------------
__global__ void init_k() {
    int i = threadIdx.x;
    if (i < E_NUM) { g_counts[i] = 0; g_cursor[i] = 0; }
}

__global__ void router_k(const float* __restrict__ x, const float* __restrict__ wg) {
    int warp = threadIdx.x >> 5;
    int lane = threadIdx.x & 31;
    int t = blockIdx.x * 8 + warp;
    if (t >= T_TOK) return;
    const float* xr = x + (size_t)t * D_DIM;
    float acc[E_NUM];
    for (int e = 0; e < E_NUM; e++) acc[e] = 0.f;
    for (int d = lane; d < D_DIM; d += 32) {
        float xv = xr[d];
        const float* w = wg + (size_t)d * E_NUM;
        for (int e = 0; e < E_NUM; e++) acc[e] = fmaf(xv, w[e], acc[e]);
    }
    for (int e = 0; e < E_NUM; e++) {
        for (int o = 16; o > 0; o >>= 1) acc[e] += __shfl_xor_sync(0xffffffffu, acc[e], o);
    }
    if (lane == 0) {
        int e0 = 0; float l0 = acc[0];
        for (int e = 1; e < E_NUM; e++) { if (acc[e] > l0) { l0 = acc[e]; e0 = e; } }
        int e1 = -1; float l1 = -INFINITY;
        for (int e = 0; e < E_NUM; e++) { if (e != e0 && acc[e] > l1) { l1 = acc[e]; e1 = e; } }
        float w0 = 1.f / (1.f + expf(l1 - l0));
        g_expert[t * 2 + 0] = e0;
        g_expert[t * 2 + 1] = e1;
        g_weight[t * 2 + 0] = w0;
        g_weight[t * 2 + 1] = 1.f - w0;
        atomicAdd(&g_counts[e0], 1);
        atomicAdd(&g_counts[e1], 1);
    }
}

__global__ void scan_k() {
    if (threadIdx.x == 0) {
        int s = 0;
        for (int e = 0; e < E_NUM; e++) { g_offsets[e] = s; s += g_counts[e]; }
        g_offsets[E_NUM] = s;
    }
}

__global__ void assign_k() {
    int i = blockIdx.x * blockDim.x + threadIdx.x;
    if (i >= NCOPIES) return;
    int e = g_expert[i];
    int p = g_offsets[e] + atomicAdd(&g_cursor[e], 1);
    g_pos[i] = p;
    g_row2tok[p] = i >> 1;
}

// ---------------- conversions ----------------
__global__ void convx_k(const float* __restrict__ x) {
    int p = blockIdx.x;
    int tok = g_row2tok[p];
    const float4* src = reinterpret_cast<const float4*>(x + (size_t)tok * D_DIM);
    int t = threadIdx.x;
    float4 a = src[t * 2];
    float4 b = src[t * 2 + 1];
    float v[8];
    v[0] = a.x; v[1] = a.y; v[2] = a.z; v[3] = a.w;
    v[4] = b.x; v[5] = b.y; v[6] = b.z; v[7] = b.w;
    __half hh[8];
    for (int i = 0; i < 8; i++) hh[i] = __float2half(v[i]);
    size_t ob = (size_t)p * D_DIM + (size_t)t * 8;
    *reinterpret_cast<uint4*>(g_ax + ob) = *reinterpret_cast<uint4*>(hh);
}

__global__ void convw1_k(const float* __restrict__ wi0, const float* __restrict__ wi1) {
    __shared__ float tile[32][33];
    int z = blockIdx.z;
    int e = z >> 1;
    int s = z & 1;
    int d0 = blockIdx.x * 32;
    int m0 = blockIdx.y * 32;
    int tx = threadIdx.x;
    int ty = threadIdx.y;
    const float* src = (s ? wi1 : wi0) + (size_t)e * D_DIM * M_DIM;
    for (int r = 0; r < 4; r++) {
        tile[ty + 8 * r][tx] = src[(size_t)(d0 + ty + 8 * r) * M_DIM + m0 + tx];
    }
    __syncthreads();
    for (int r = 0; r < 4; r++) {
        int mloc = ty + 8 * r;
        int n = 2 * (m0 + mloc) + s;
        float v = tile[tx][mloc];
        size_t o = ((size_t)e * 2048 + (size_t)n) * D_DIM + d0 + tx;
        g_w1[o] = __float2half(v);
    }
}

__global__ void convw2_k(const float* __restrict__ wo) {
    __shared__ float tile[32][33];
    int e = blockIdx.z;
    int m0 = blockIdx.x * 32;
    int d0 = blockIdx.y * 32;
    int tx = threadIdx.x;
    int ty = threadIdx.y;
    const float* src = wo + (size_t)e * M_DIM * D_DIM;
    for (int r = 0; r < 4; r++) {
        tile[ty + 8 * r][tx] = src[(size_t)(m0 + ty + 8 * r) * D_DIM + d0 + tx];
    }
    __syncthreads();
    for (int r = 0; r < 4; r++) {
        int n = d0 + ty + 8 * r;
        float v = tile[tx][ty + 8 * r];
        size_t o = ((size_t)e * D_DIM + (size_t)n) * M_DIM + m0 + tx;
        g_w2[o] = __float2half(v);
    }
}

// ---------------- mma.sync grouped GEMM ----------------
// CTA tile 128(M) x 128(N), BK=32, 8 warps (2x4), warp tile 64x32.
// Smem rows padded to 80B -> conflict-free ldmatrix.
// Single fp16 term: A*B.
#define ROWB      80
#define A_BYTES   (128*ROWB)     // 10240
#define STG_BYTES (2*A_BYTES)    // A, B = 20480
#define NSTAGE    3
#define SMEM_REQ  (NSTAGE*STG_BYTES)

__device__ __forceinline__ void load_stage(
    uint32_t sbase, int stg, int tx,
    const __half* A, const __half* B,
    int aRowBase, int cnt, size_t bRowBase, int KT, int k0)
{
    uint32_t s0 = sbase + (uint32_t)stg * STG_BYTES;
    for (int i = 0; i < 2; i++) {
        int id = tx + i * 256;
        int row = id >> 2;
        int cc = id & 3;
        int rclamp = (row < cnt) ? row : (cnt - 1);
        size_t goA = (size_t)(aRowBase + rclamp) * KT + k0 + cc * 8;
        uint32_t off = (uint32_t)(row * ROWB + cc * 16);
        cp_async16(s0 + off, A + goA);
        size_t goB = (bRowBase + (size_t)row) * KT + k0 + cc * 8;
        cp_async16(s0 + A_BYTES + off, B + goB);
    }
}

__device__ __forceinline__ void gemm_mainloop(
    uint32_t sbase, int tx,
    const __half* A, const __half* B,
    int aRowBase, int cnt, size_t bRowBase, int KT,
    float acc[4][4][4])
{
    const int NITER = KT / 32;
    int wid = tx >> 5;
    int lane = tx & 31;
    int wm = wid >> 2;
    int wn = wid & 3;
    int l15 = lane & 15;
    int l16 = lane >> 4;

    uint32_t aoff = (uint32_t)((wm * 64 + l15) * ROWB + l16 * 16);
    uint32_t boff = (uint32_t)(A_BYTES + (wn * 32 + l15) * ROWB + l16 * 16);

    load_stage(sbase, 0, tx, A, B, aRowBase, cnt, bRowBase, KT, 0);
    cp_commit();
    load_stage(sbase, 1, tx, A, B, aRowBase, cnt, bRowBase, KT, 32);
    cp_commit();

    for (int it = 0; it < NITER; it++) {
        cp_wait1();
        __syncthreads();
        if (it + 2 < NITER) {
            load_stage(sbase, (it + 2) % NSTAGE, tx, A, B,
                       aRowBase, cnt, bRowBase, KT, (it + 2) * 32);
        }
        cp_commit();

        uint32_t s0 = sbase + (uint32_t)(it % NSTAGE) * STG_BYTES;
        for (int kk = 0; kk < 2; kk++) {
            uint32_t ah[4][4], bb[2][4];
            for (int mt = 0; mt < 4; mt++) {
                uint32_t ad = s0 + aoff + (uint32_t)(mt * 16 * ROWB + kk * 32);
                ldm_x4(ah[mt][0], ah[mt][1], ah[mt][2], ah[mt][3], ad);
            }
            for (int g = 0; g < 2; g++) {
                uint32_t bd = s0 + boff + (uint32_t)(g * 16 * ROWB + kk * 32);
                ldm_x4(bb[g][0], bb[g][1], bb[g][2], bb[g][3], bd);
            }
            for (int mt = 0; mt < 4; mt++) {
                for (int nt = 0; nt < 4; nt++) {
                    int g = nt >> 1;
                    int p = nt & 1;
                    mma_f16(acc[mt][nt], ah[mt], bb[g][p], bb[g][p + 2]);
                }
            }
        }
        __syncthreads();
    }
}

// GEMM1: K=2048, N=2048 interleaved, fused silu epilogue -> g_inter fp16
__global__ void __launch_bounds__(256, 1) gemm1_mma() {
    int e = blockIdx.z;
    int base = g_offsets[e];
    int cnt  = g_offsets[e + 1] - base;
    int row0 = blockIdx.y * 128;
    if (row0 >= cnt) return;
    int col0 = blockIdx.x * 128;

    extern __shared__ char smraw[];
    uint32_t sbase = smem_u32(smraw);
    int tx = threadIdx.x;

    float acc[4][4][4];
    for (int a = 0; a < 4; a++)
        for (int b = 0; b < 4; b++)
            for (int c = 0; c < 4; c++) acc[a][b][c] = 0.f;

    size_t bRowBase = (size_t)e * 2048 + col0;
    gemm_mainloop(sbase, tx, g_ax, g_w1, base + row0, cnt - row0, bRowBase, 2048, acc);

    int wid = tx >> 5;
    int lane = tx & 31;
    int wm = wid >> 2;
    int wn = wid & 3;
    int qrow = lane >> 2;
    int qcol = lane & 3;
    for (int mt = 0; mt < 4; mt++) {
        for (int nt = 0; nt < 4; nt++) {
            int r0 = row0 + wm * 64 + mt * 16 + qrow;
            int icol = ((col0 + wn * 32 + nt * 8) >> 1) + qcol;
            float* c = acc[mt][nt];
            if (r0 < cnt) {
                float v = c[0] / (1.f + __expf(-c[0])) * c[1];
                g_inter[(size_t)(base + r0) * M_DIM + icol] = __float2half(v);
            }
            int r1 = r0 + 8;
            if (r1 < cnt) {
                float v = c[2] / (1.f + __expf(-c[2])) * c[3];
                g_inter[(size_t)(base + r1) * M_DIM + icol] = __float2half(v);
            }
        }
    }
}

// GEMM2: K=1024, N=2048, fp32 epilogue -> g_outsorted
__global__ void __launch_bounds__(256, 1) gemm2_mma() {
    int e = blockIdx.z;
    int base = g_offsets[e];
    int cnt  = g_offsets[e + 1] - base;
    int row0 = blockIdx.y * 128;
    if (row0 >= cnt) return;
    int col0 = blockIdx.x * 128;

    extern __shared__ char smraw[];
    uint32_t sbase = smem_u32(smraw);
    int tx = threadIdx.x;

    float acc[4][4][4];
    for (int a = 0; a < 4; a++)
        for (int b = 0; b < 4; b++)
            for (int c = 0; c < 4; c++) acc[a][b][c] = 0.f;

    size_t bRowBase = (size_t)e * 2048 + col0;
    gemm_mainloop(sbase, tx, g_inter, g_w2, base + row0, cnt - row0, bRowBase, 1024, acc);

    int wid = tx >> 5;
    int lane = tx & 31;
    int wm = wid >> 2;
    int wn = wid & 3;
    int qrow = lane >> 2;
    int qcol = lane & 3;
    for (int mt = 0; mt < 4; mt++) {
        for (int nt = 0; nt < 4; nt++) {
            int r0 = row0 + wm * 64 + mt * 16 + qrow;
            int colg = col0 + wn * 32 + nt * 8 + qcol * 2;
            float* c = acc[mt][nt];
            if (r0 < cnt) {
                float2 v; v.x = c[0]; v.y = c[1];
                *reinterpret_cast<float2*>(g_outsorted + (size_t)(base + r0) * D_DIM + colg) = v;
            }
            int r1 = r0 + 8;
            if (r1 < cnt) {
                float2 v; v.x = c[2]; v.y = c[3];
                *reinterpret_cast<float2*>(g_outsorted + (size_t)(base + r1) * D_DIM + colg) = v;
            }
        }
    }
}

// ---------------- combine ----------------
__global__ void combine_k(float* __restrict__ out) {
    int t = blockIdx.x;
    float w0 = g_weight[t * 2 + 0];
    float w1 = g_weight[t * 2 + 1];
    const float* p0 = g_outsorted + (size_t)g_pos[t * 2 + 0] * D_DIM;
    const float* p1 = g_outsorted + (size_t)g_pos[t * 2 + 1] * D_DIM;
    float* o = out + (size_t)t * D_DIM;
    for (int d = threadIdx.x * 4; d < D_DIM; d += blockDim.x * 4) {
        float4 a = *reinterpret_cast<const float4*>(p0 + d);
        float4 b = *reinterpret_cast<const float4*>(p1 + d);
        float4 r;
        r.x = w0 * a.x + w1 * b.x;
        r.y = w0 * a.y + w1 * b.y;
        r.z = w0 * a.z + w1 * b.z;
        r.w = w0 * a.w + w1 * b.w;
        *reinterpret_cast<float4*>(o + d) = r;
    }
}

// ---------------- launch ----------------
extern "C" void kernel_launch(void* const* d_in, const int* in_sizes, int n_in,
                              void* d_out, int out_size) {
    const float* x   = (const float*)d_in[0];
    const float* wg  = (const float*)d_in[1];
    const float* wi0 = (const float*)d_in[2];
    const float* wi1 = (const float*)d_in[3];
    const float* wo  = (const float*)d_in[4];
    float* out = (float*)d_out;

    cudaFuncSetAttribute(gemm1_mma, cudaFuncAttributeMaxDynamicSharedMemorySize, SMEM_REQ);
    cudaFuncSetAttribute(gemm2_mma, cudaFuncAttributeMaxDynamicSharedMemorySize, SMEM_REQ);

    init_k<<<1, 32>>>();
    router_k<<<T_TOK / 8, 256>>>(x, wg);
    scan_k<<<1, 32>>>();
    assign_k<<<NCOPIES / 256, 256>>>();

    convx_k<<<NCOPIES, 256>>>(x);
    convw1_k<<<dim3(D_DIM / 32, M_DIM / 32, E_NUM * 2), dim3(32, 8)>>>(wi0, wi1);
    convw2_k<<<dim3(M_DIM / 32, D_DIM / 32, E_NUM), dim3(32, 8)>>>(wo);

    dim3 g1(2 * M_DIM / 128, NCOPIES / 128, E_NUM);   // (16, 128, 8)
    gemm1_mma<<<g1, 256, SMEM_REQ>>>();

    dim3 g2(D_DIM / 128, NCOPIES / 128, E_NUM);       // (16, 128, 8)
    gemm2_mma<<<g2, 256, SMEM_REQ>>>();

    combine_k<<<T_TOK, 256>>>(out);
}

// round 8
// speedup vs baseline: 4.4280x; 1.0728x over previous
#include <cuda_runtime.h>
#include <cuda_fp16.h>
#include <cstdint>
#include <math.h>

// ---------------- Problem dims (fixed) ----------------
#define T_TOK   8192
#define D_DIM   2048
#define M_DIM   1024
#define E_NUM   8
#define NCOPIES (T_TOK*2)

// ---------------- Scratch ----------------
__device__ int   g_counts[E_NUM];
__device__ int   g_offsets[E_NUM + 1];
__device__ int   g_cursor[E_NUM];
__device__ int   g_expert[NCOPIES];
__device__ float g_weight[NCOPIES];
__device__ int   g_pos[NCOPIES];
__device__ int   g_row2tok[NCOPIES];

__device__ __half g_ax[(size_t)NCOPIES * D_DIM];
__device__ __half g_w1[(size_t)E_NUM * 2 * M_DIM * D_DIM];   // [E][N=2048 interleaved][K=2048]
__device__ __half g_w2[(size_t)E_NUM * D_DIM * M_DIM];       // [E][N=2048][K=1024]
__device__ __half g_inter[(size_t)NCOPIES * M_DIM];
__device__ __half g_outsorted[(size_t)NCOPIES * D_DIM];

// ---------------- helpers ----------------
__device__ __forceinline__ uint32_t smem_u32(const void* p) {
    uint32_t a;
    asm("{ .reg .u64 t; cvta.to.shared.u64 t, %1; cvt.u32.u64 %0, t; }" : "=r"(a) : "l"(p));
    return a;
}
__device__ __forceinline__ void cp_async16(uint32_t dst, const void* src) {
    asm volatile("cp.async.cg.shared.global [%0], [%1], 16;" :: "r"(dst), "l"(src) : "memory");
}
__device__ __forceinline__ void cp_commit() {
    asm volatile("cp.async.commit_group;" ::: "memory");
}
__device__ __forceinline__ void cp_wait2() {
    asm volatile("cp.async.wait_group 2;" ::: "memory");
}
__device__ __forceinline__ void ldm_x4(uint32_t& r0, uint32_t& r1, uint32_t& r2, uint32_t& r3, uint32_t addr) {
    asm volatile("ldmatrix.sync.aligned.m8n8.x4.shared.b16 {%0,%1,%2,%3}, [%4];"
                 : "=r"(r0), "=r"(r1), "=r"(r2), "=r"(r3) : "r"(addr));
}
__device__ __forceinline__ void mma_f16(float* c, const uint32_t* a, uint32_t b0, uint32_t b1) {
    asm volatile(
        "mma.sync.aligned.m16n8k16.row.col.f32.f16.f16.f32 "
        "{%0,%1,%2,%3}, {%4,%5,%6,%7}, {%8,%9}, {%0,%1,%2,%3};"
        : "+f"(c[0]), "+f"(c[1]), "+f"(c[2]), "+f"(c[3])
        : "r"(a[0]), "r"(a[1]), "r"(a[2]), "r"(a[3]), "r"(b0), "r"(b1));
}

// ---------------- routing ----------------
__global__ void init_k() {
    int i = threadIdx.x;
    if (i < E_NUM) { g_counts[i] = 0; g_cursor[i] = 0; }
}

__global__ void router_k(const float* __restrict__ x, const float* __restrict__ wg) {
    int warp = threadIdx.x >> 5;
    int lane = threadIdx.x & 31;
    int t = blockIdx.x * 8 + warp;
    if (t >= T_TOK) return;
    const float* xr = x + (size_t)t * D_DIM;
    float acc[E_NUM];
    for (int e = 0; e < E_NUM; e++) acc[e] = 0.f;
    for (int d = lane; d < D_DIM; d += 32) {
        float xv = xr[d];
        const float* w = wg + (size_t)d * E_NUM;
        for (int e = 0; e < E_NUM; e++) acc[e] = fmaf(xv, w[e], acc[e]);
    }
    for (int e = 0; e < E_NUM; e++) {
        for (int o = 16; o > 0; o >>= 1) acc[e] += __shfl_xor_sync(0xffffffffu, acc[e], o);
    }
    if (lane == 0) {
        int e0 = 0; float l0 = acc[0];
        for (int e = 1; e < E_NUM; e++) { if (acc[e] > l0) { l0 = acc[e]; e0 = e; } }
        int e1 = -1; float l1 = -INFINITY;
        for (int e = 0; e < E_NUM; e++) { if (e != e0 && acc[e] > l1) { l1 = acc[e]; e1 = e; } }
        float w0 = 1.f / (1.f + expf(l1 - l0));
        g_expert[t * 2 + 0] = e0;
        g_expert[t * 2 + 1] = e1;
        g_weight[t * 2 + 0] = w0;
        g_weight[t * 2 + 1] = 1.f - w0;
        atomicAdd(&g_counts[e0], 1);
        atomicAdd(&g_counts[e1], 1);
    }
}

__global__ void scan_k() {
    if (threadIdx.x == 0) {
        int s = 0;
        for (int e = 0; e < E_NUM; e++) { g_offsets[e] = s; s += g_counts[e]; }
        g_offsets[E_NUM] = s;
    }
}

__global__ void assign_k() {
    int i = blockIdx.x * blockDim.x + threadIdx.x;
    if (i >= NCOPIES) return;
    int e = g_expert[i];
    int p = g_offsets[e] + atomicAdd(&g_cursor[e], 1);
    g_pos[i] = p;
    g_row2tok[p] = i >> 1;
}

// ---------------- conversions ----------------
__global__ void convx_k(const float* __restrict__ x) {
    int p = blockIdx.x;
    int tok = g_row2tok[p];
    const float4* src = reinterpret_cast<const float4*>(x + (size_t)tok * D_DIM);
    int t = threadIdx.x;
    float4 a = src[t * 2];
    float4 b = src[t * 2 + 1];
    float v[8];
    v[0] = a.x; v[1] = a.y; v[2] = a.z; v[3] = a.w;
    v[4] = b.x; v[5] = b.y; v[6] = b.z; v[7] = b.w;
    __half hh[8];
    for (int i = 0; i < 8; i++) hh[i] = __float2half(v[i]);
    size_t ob = (size_t)p * D_DIM + (size_t)t * 8;
    *reinterpret_cast<uint4*>(g_ax + ob) = *reinterpret_cast<uint4*>(hh);
}

__global__ void convw1_k(const float* __restrict__ wi0, const float* __restrict__ wi1) {
    __shared__ float tile[32][33];
    int z = blockIdx.z;
    int e = z >> 1;
    int s = z & 1;
    int d0 = blockIdx.x * 32;
    int m0 = blockIdx.y * 32;
    int tx = threadIdx.x;
    int ty = threadIdx.y;
    const float* src = (s ? wi1 : wi0) + (size_t)e * D_DIM * M_DIM;
    for (int r = 0; r < 4; r++) {
        tile[ty + 8 * r][tx] = src[(size_t)(d0 + ty + 8 * r) * M_DIM + m0 + tx];
    }
    __syncthreads();
    for (int r = 0; r < 4; r++) {
        int mloc = ty + 8 * r;
        int n = 2 * (m0 + mloc) + s;
        float v = tile[tx][mloc];
        size_t o = ((size_t)e * 2048 + (size_t)n) * D_DIM + d0 + tx;
        g_w1[o] = __float2half(v);
    }
}

__global__ void convw2_k(const float* __restrict__ wo) {
    __shared__ float tile[32][33];
    int e = blockIdx.z;
    int m0 = blockIdx.x * 32;
    int d0 = blockIdx.y * 32;
    int tx = threadIdx.x;
    int ty = threadIdx.y;
    const float* src = wo + (size_t)e * M_DIM * D_DIM;
    for (int r = 0; r < 4; r++) {
        tile[ty + 8 * r][tx] = src[(size_t)(m0 + ty + 8 * r) * D_DIM + d0 + tx];
    }
    __syncthreads();
    for (int r = 0; r < 4; r++) {
        int n = d0 + ty + 8 * r;
        float v = tile[tx][ty + 8 * r];
        size_t o = ((size_t)e * D_DIM + (size_t)n) * M_DIM + m0 + tx;
        g_w2[o] = __float2half(v);
    }
}

// ---------------- mma.sync grouped GEMM ----------------
// CTA tile 128(M) x 128(N), BK=32, 8 warps (2x4), warp tile 64x32.
// 4-stage cp.async pipeline, distance 2, ONE __syncthreads per iteration.
#define ROWB      80
#define A_BYTES   (128*ROWB)     // 10240
#define STG_BYTES (2*A_BYTES)    // A, B = 20480
#define NSTAGE    4
#define SMEM_REQ  (NSTAGE*STG_BYTES)

__device__ __forceinline__ void load_stage(
    uint32_t sbase, int stg, int tx,
    const __half* A, const __half* B,
    int aRowBase, int cnt, size_t bRowBase, int KT, int k0)
{
    uint32_t s0 = sbase + (uint32_t)stg * STG_BYTES;
    for (int i = 0; i < 2; i++) {
        int id = tx + i * 256;
        int row = id >> 2;
        int cc = id & 3;
        int rclamp = (row < cnt) ? row : (cnt - 1);
        size_t goA = (size_t)(aRowBase + rclamp) * KT + k0 + cc * 8;
        uint32_t off = (uint32_t)(row * ROWB + cc * 16);
        cp_async16(s0 + off, A + goA);
        size_t goB = (bRowBase + (size_t)row) * KT + k0 + cc * 8;
        cp_async16(s0 + A_BYTES + off, B + goB);
    }
}

__device__ __forceinline__ void gemm_mainloop(
    uint32_t sbase, int tx,
    const __half* A, const __half* B,
    int aRowBase, int cnt, size_t bRowBase, int KT,
    float acc[4][4][4])
{
    const int NITER = KT / 32;
    int wid = tx >> 5;
    int lane = tx & 31;
    int wm = wid >> 2;
    int wn = wid & 3;
    int l15 = lane & 15;
    int l16 = lane >> 4;

    uint32_t aoff = (uint32_t)((wm * 64 + l15) * ROWB + l16 * 16);
    uint32_t boff = (uint32_t)(A_BYTES + (wn * 32 + l15) * ROWB + l16 * 16);

    load_stage(sbase, 0, tx, A, B, aRowBase, cnt, bRowBase, KT, 0);
    cp_commit();
    load_stage(sbase, 1, tx, A, B, aRowBase, cnt, bRowBase, KT, 32);
    cp_commit();

    for (int it = 0; it < NITER; it++) {
        if (it + 2 < NITER) {
            load_stage(sbase, (it + 2) % NSTAGE, tx, A, B,
                       aRowBase, cnt, bRowBase, KT, (it + 2) * 32);
        }
        cp_commit();
        cp_wait2();
        __syncthreads();

        uint32_t s0 = sbase + (uint32_t)(it % NSTAGE) * STG_BYTES;
        for (int kk = 0; kk < 2; kk++) {
            uint32_t ah[4][4], bb[2][4];
            for (int mt = 0; mt < 4; mt++) {
                uint32_t ad = s0 + aoff + (uint32_t)(mt * 16 * ROWB + kk * 32);
                ldm_x4(ah[mt][0], ah[mt][1], ah[mt][2], ah[mt][3], ad);
            }
            for (int g = 0; g < 2; g++) {
                uint32_t bd = s0 + boff + (uint32_t)(g * 16 * ROWB + kk * 32);
                ldm_x4(bb[g][0], bb[g][1], bb[g][2], bb[g][3], bd);
            }
            for (int mt = 0; mt < 4; mt++) {
                for (int nt = 0; nt < 4; nt++) {
                    int g = nt >> 1;
                    int p = nt & 1;
                    mma_f16(acc[mt][nt], ah[mt], bb[g][p], bb[g][p + 2]);
                }
            }
        }
    }
}

// GEMM1: K=2048, N=2048 interleaved, fused silu epilogue -> g_inter fp16
__global__ void __launch_bounds__(256, 1) gemm1_mma() {
    int e = blockIdx.z;
    int base = g_offsets[e];
    int cnt  = g_offsets[e + 1] - base;
    int row0 = blockIdx.y * 128;
    if (row0 >= cnt) return;
    int col0 = blockIdx.x * 128;

    extern __shared__ char smraw[];
    uint32_t sbase = smem_u32(smraw);
    int tx = threadIdx.x;

    float acc[4][4][4];
    for (int a = 0; a < 4; a++)
        for (int b = 0; b < 4; b++)
            for (int c = 0; c < 4; c++) acc[a][b][c] = 0.f;

    size_t bRowBase = (size_t)e * 2048 + col0;
    gemm_mainloop(sbase, tx, g_ax, g_w1, base + row0, cnt - row0, bRowBase, 2048, acc);

    int wid = tx >> 5;
    int lane = tx & 31;
    int wm = wid >> 2;
    int wn = wid & 3;
    int qrow = lane >> 2;
    int qcol = lane & 3;
    for (int mt = 0; mt < 4; mt++) {
        for (int nt = 0; nt < 4; nt++) {
            int r0 = row0 + wm * 64 + mt * 16 + qrow;
            int icol = ((col0 + wn * 32 + nt * 8) >> 1) + qcol;
            float* c = acc[mt][nt];
            if (r0 < cnt) {
                float v = c[0] / (1.f + __expf(-c[0])) * c[1];
                g_inter[(size_t)(base + r0) * M_DIM + icol] = __float2half(v);
            }
            int r1 = r0 + 8;
            if (r1 < cnt) {
                float v = c[2] / (1.f + __expf(-c[2])) * c[3];
                g_inter[(size_t)(base + r1) * M_DIM + icol] = __float2half(v);
            }
        }
    }
}

// GEMM2: K=1024, N=2048, fp16 epilogue -> g_outsorted
__global__ void __launch_bounds__(256, 1) gemm2_mma() {
    int e = blockIdx.z;
    int base = g_offsets[e];
    int cnt  = g_offsets[e + 1] - base;
    int row0 = blockIdx.y * 128;
    if (row0 >= cnt) return;
    int col0 = blockIdx.x * 128;

    extern __shared__ char smraw[];
    uint32_t sbase = smem_u32(smraw);
    int tx = threadIdx.x;

    float acc[4][4][4];
    for (int a = 0; a < 4; a++)
        for (int b = 0; b < 4; b++)
            for (int c = 0; c < 4; c++) acc[a][b][c] = 0.f;

    size_t bRowBase = (size_t)e * 2048 + col0;
    gemm_mainloop(sbase, tx, g_inter, g_w2, base + row0, cnt - row0, bRowBase, 1024, acc);

    int wid = tx >> 5;
    int lane = tx & 31;
    int wm = wid >> 2;
    int wn = wid & 3;
    int qrow = lane >> 2;
    int qcol = lane & 3;
    for (int mt = 0; mt < 4; mt++) {
        for (int nt = 0; nt < 4; nt++) {
            int r0 = row0 + wm * 64 + mt * 16 + qrow;
            int colg = col0 + wn * 32 + nt * 8 + qcol * 2;
            float* c = acc[mt][nt];
            if (r0 < cnt) {
                __half2 v = __floats2half2_rn(c[0], c[1]);
                *reinterpret_cast<__half2*>(g_outsorted + (size_t)(base + r0) * D_DIM + colg) = v;
            }
            int r1 = r0 + 8;
            if (r1 < cnt) {
                __half2 v = __floats2half2_rn(c[2], c[3]);
                *reinterpret_cast<__half2*>(g_outsorted + (size_t)(base + r1) * D_DIM + colg) = v;
            }
        }
    }
}

// ---------------- combine (fp16 inputs) ----------------
__global__ void combine_k(float* __restrict__ out) {
    int t = blockIdx.x;
    float w0 = g_weight[t * 2 + 0];
    float w1 = g_weight[t * 2 + 1];
    const __half* p0 = g_outsorted + (size_t)g_pos[t * 2 + 0] * D_DIM;
    const __half* p1 = g_outsorted + (size_t)g_pos[t * 2 + 1] * D_DIM;
    float* o = out + (size_t)t * D_DIM;
    int d = threadIdx.x * 8;
    {
        uint4 ua = *reinterpret_cast<const uint4*>(p0 + d);
        uint4 ub = *reinterpret_cast<const uint4*>(p1 + d);
        const __half2* ha = reinterpret_cast<const __half2*>(&ua);
        const __half2* hb = reinterpret_cast<const __half2*>(&ub);
        float rr[8];
        for (int i = 0; i < 4; i++) {
            float2 fa = __half22float2(ha[i]);
            float2 fb = __half22float2(hb[i]);
            rr[2 * i + 0] = w0 * fa.x + w1 * fb.x;
            rr[2 * i + 1] = w0 * fa.y + w1 * fb.y;
        }
        *reinterpret_cast<float4*>(o + d)     = make_float4(rr[0], rr[1], rr[2], rr[3]);
        *reinterpret_cast<float4*>(o + d + 4) = make_float4(rr[4], rr[5], rr[6], rr[7]);
    }
}

// ---------------- launch ----------------
extern "C" void kernel_launch(void* const* d_in, const int* in_sizes, int n_in,
                              void* d_out, int out_size) {
    const float* x   = (const float*)d_in[0];
    const float* wg  = (const float*)d_in[1];
    const float* wi0 = (const float*)d_in[2];
    const float* wi1 = (const float*)d_in[3];
    const float* wo  = (const float*)d_in[4];
    float* out = (float*)d_out;

    cudaFuncSetAttribute(gemm1_mma, cudaFuncAttributeMaxDynamicSharedMemorySize, SMEM_REQ);
    cudaFuncSetAttribute(gemm2_mma, cudaFuncAttributeMaxDynamicSharedMemorySize, SMEM_REQ);

    init_k<<<1, 32>>>();
    router_k<<<T_TOK / 8, 256>>>(x, wg);
    scan_k<<<1, 32>>>();
    assign_k<<<NCOPIES / 256, 256>>>();

    convx_k<<<NCOPIES, 256>>>(x);
    convw1_k<<<dim3(D_DIM / 32, M_DIM / 32, E_NUM * 2), dim3(32, 8)>>>(wi0, wi1);
    convw2_k<<<dim3(M_DIM / 32, D_DIM / 32, E_NUM), dim3(32, 8)>>>(wo);

    dim3 g1(2 * M_DIM / 128, NCOPIES / 128, E_NUM);   // (16, 128, 8)
    gemm1_mma<<<g1, 256, SMEM_REQ>>>();

    dim3 g2(D_DIM / 128, NCOPIES / 128, E_NUM);       // (16, 128, 8)
    gemm2_mma<<<g2, 256, SMEM_REQ>>>();

    combine_k<<<T_TOK, 256>>>(out);
}

// round 9
// speedup vs baseline: 4.4524x; 1.0055x over previous
#include <cuda_runtime.h>
#include <cuda_fp16.h>
#include <cstdint>
#include <math.h>

// ---------------- Problem dims (fixed) ----------------
#define T_TOK   8192
#define D_DIM   2048
#define M_DIM   1024
#define E_NUM   8
#define NCOPIES (T_TOK*2)

// ---------------- Scratch ----------------
__device__ int   g_counts[E_NUM];
__device__ int   g_offsets[E_NUM + 1];
__device__ int   g_cursor[E_NUM];
__device__ int   g_expert[NCOPIES];
__device__ float g_weight[NCOPIES];
__device__ int   g_pos[NCOPIES];
__device__ int   g_row2tok[NCOPIES];

__device__ __half g_xh[(size_t)T_TOK * D_DIM];               // x in fp16, token order
__device__ __half g_w1[(size_t)E_NUM * 2 * M_DIM * D_DIM];   // [E][N=2048 interleaved][K=2048]
__device__ __half g_w2[(size_t)E_NUM * D_DIM * M_DIM];       // [E][N=2048][K=1024]
__device__ __half g_inter[(size_t)NCOPIES * M_DIM];
__device__ __half g_outsorted[(size_t)NCOPIES * D_DIM];

// ---------------- helpers ----------------
__device__ __forceinline__ uint32_t smem_u32(const void* p) {
    uint32_t a;
    asm("{ .reg .u64 t; cvta.to.shared.u64 t, %1; cvt.u32.u64 %0, t; }" : "=r"(a) : "l"(p));
    return a;
}
__device__ __forceinline__ void cp_async16(uint32_t dst, const void* src) {
    asm volatile("cp.async.cg.shared.global [%0], [%1], 16;" :: "r"(dst), "l"(src) : "memory");
}
__device__ __forceinline__ void cp_commit() {
    asm volatile("cp.async.commit_group;" ::: "memory");
}
__device__ __forceinline__ void cp_wait2() {
    asm volatile("cp.async.wait_group 2;" ::: "memory");
}
__device__ __forceinline__ void ldm_x4(uint32_t& r0, uint32_t& r1, uint32_t& r2, uint32_t& r3, uint32_t addr) {
    asm volatile("ldmatrix.sync.aligned.m8n8.x4.shared.b16 {%0,%1,%2,%3}, [%4];"
                 : "=r"(r0), "=r"(r1), "=r"(r2), "=r"(r3) : "r"(addr));
}
__device__ __forceinline__ void mma_f16(float* c, const uint32_t* a, uint32_t b0, uint32_t b1) {
    asm volatile(
        "mma.sync.aligned.m16n8k16.row.col.f32.f16.f16.f32 "
        "{%0,%1,%2,%3}, {%4,%5,%6,%7}, {%8,%9}, {%0,%1,%2,%3};"
        : "+f"(c[0]), "+f"(c[1]), "+f"(c[2]), "+f"(c[3])
        : "r"(a[0]), "r"(a[1]), "r"(a[2]), "r"(a[3]), "r"(b0), "r"(b1));
}

// ---------------- routing ----------------
__global__ void init_k() {
    int i = threadIdx.x;
    if (i < E_NUM) { g_counts[i] = 0; g_cursor[i] = 0; }
}

__global__ void router_k(const float* __restrict__ x, const float* __restrict__ wg) {
    int warp = threadIdx.x >> 5;
    int lane = threadIdx.x & 31;
    int t = blockIdx.x * 8 + warp;
    if (t >= T_TOK) return;
    const float* xr = x + (size_t)t * D_DIM;
    float acc[E_NUM];
    for (int e = 0; e < E_NUM; e++) acc[e] = 0.f;
    for (int d = lane; d < D_DIM; d += 32) {
        float xv = xr[d];
        const float* w = wg + (size_t)d * E_NUM;
        for (int e = 0; e < E_NUM; e++) acc[e] = fmaf(xv, w[e], acc[e]);
    }
    for (int e = 0; e < E_NUM; e++) {
        for (int o = 16; o > 0; o >>= 1) acc[e] += __shfl_xor_sync(0xffffffffu, acc[e], o);
    }
    if (lane == 0) {
        int e0 = 0; float l0 = acc[0];
        for (int e = 1; e < E_NUM; e++) { if (acc[e] > l0) { l0 = acc[e]; e0 = e; } }
        int e1 = -1; float l1 = -INFINITY;
        for (int e = 0; e < E_NUM; e++) { if (e != e0 && acc[e] > l1) { l1 = acc[e]; e1 = e; } }
        float w0 = 1.f / (1.f + expf(l1 - l0));
        g_expert[t * 2 + 0] = e0;
        g_expert[t * 2 + 1] = e1;
        g_weight[t * 2 + 0] = w0;
        g_weight[t * 2 + 1] = 1.f - w0;
        atomicAdd(&g_counts[e0], 1);
        atomicAdd(&g_counts[e1], 1);
    }
}

__global__ void scan_k() {
    if (threadIdx.x == 0) {
        int s = 0;
        for (int e = 0; e < E_NUM; e++) { g_offsets[e] = s; s += g_counts[e]; }
        g_offsets[E_NUM] = s;
    }
}

__global__ void assign_k() {
    int i = blockIdx.x * blockDim.x + threadIdx.x;
    if (i >= NCOPIES) return;
    int e = g_expert[i];
    int p = g_offsets[e] + atomicAdd(&g_cursor[e], 1);
    g_pos[i] = p;
    g_row2tok[p] = i >> 1;
}

// ---------------- conversions ----------------
// x -> fp16, token order (no gather; gemm1 gathers at load time)
__global__ void convxtok_k(const float* __restrict__ x) {
    size_t i = ((size_t)blockIdx.x * blockDim.x + threadIdx.x) * 8;
    float4 a = *reinterpret_cast<const float4*>(x + i);
    float4 b = *reinterpret_cast<const float4*>(x + i + 4);
    __half hh[8];
    hh[0] = __float2half(a.x); hh[1] = __float2half(a.y);
    hh[2] = __float2half(a.z); hh[3] = __float2half(a.w);
    hh[4] = __float2half(b.x); hh[5] = __float2half(b.y);
    hh[6] = __float2half(b.z); hh[7] = __float2half(b.w);
    *reinterpret_cast<uint4*>(g_xh + i) = *reinterpret_cast<uint4*>(hh);
}

__global__ void convw1_k(const float* __restrict__ wi0, const float* __restrict__ wi1) {
    __shared__ float tile[32][33];
    int z = blockIdx.z;
    int e = z >> 1;
    int s = z & 1;
    int d0 = blockIdx.x * 32;
    int m0 = blockIdx.y * 32;
    int tx = threadIdx.x;
    int ty = threadIdx.y;
    const float* src = (s ? wi1 : wi0) + (size_t)e * D_DIM * M_DIM;
    for (int r = 0; r < 4; r++) {
        tile[ty + 8 * r][tx] = src[(size_t)(d0 + ty + 8 * r) * M_DIM + m0 + tx];
    }
    __syncthreads();
    for (int r = 0; r < 4; r++) {
        int mloc = ty + 8 * r;
        int n = 2 * (m0 + mloc) + s;
        float v = tile[tx][mloc];
        size_t o = ((size_t)e * 2048 + (size_t)n) * D_DIM + d0 + tx;
        g_w1[o] = __float2half(v);
    }
}

__global__ void convw2_k(const float* __restrict__ wo) {
    __shared__ float tile[32][33];
    int e = blockIdx.z;
    int m0 = blockIdx.x * 32;
    int d0 = blockIdx.y * 32;
    int tx = threadIdx.x;
    int ty = threadIdx.y;
    const float* src = wo + (size_t)e * M_DIM * D_DIM;
    for (int r = 0; r < 4; r++) {
        tile[ty + 8 * r][tx] = src[(size_t)(m0 + ty + 8 * r) * D_DIM + d0 + tx];
    }
    __syncthreads();
    for (int r = 0; r < 4; r++) {
        int n = d0 + ty + 8 * r;
        float v = tile[tx][ty + 8 * r];
        size_t o = ((size_t)e * D_DIM + (size_t)n) * M_DIM + m0 + tx;
        g_w2[o] = __float2half(v);
    }
}

// ---------------- mma.sync grouped GEMM ----------------
// CTA tile 128(M) x 128(N), BK=32, 8 warps (2x4), warp tile 64x32.
// 4-stage cp.async pipeline, distance 2, ONE __syncthreads per iteration.
// Occupancy 2 (2 x 80KB smem per SM).
#define ROWB      80
#define A_BYTES   (128*ROWB)     // 10240
#define STG_BYTES (2*A_BYTES)    // A, B = 20480
#define NSTAGE    4
#define TILE_SMEM (NSTAGE*STG_BYTES)
#define SMEM_REQ  (TILE_SMEM + 512)   // + row index table

// arow_tab: smem table of absolute A row indices (or nullptr -> aRowBase+row clamped)
__device__ __forceinline__ void load_stage(
    uint32_t sbase, int stg, int tx,
    const __half* A, const __half* B,
    const int* arow_tab, int aRowBase, int cnt, size_t bRowBase, int KT, int k0)
{
    uint32_t s0 = sbase + (uint32_t)stg * STG_BYTES;
    for (int i = 0; i < 2; i++) {
        int id = tx + i * 256;
        int row = id >> 2;
        int cc = id & 3;
        int arow;
        if (arow_tab) {
            arow = arow_tab[row];
        } else {
            arow = aRowBase + ((row < cnt) ? row : (cnt - 1));
        }
        size_t goA = (size_t)arow * KT + k0 + cc * 8;
        uint32_t off = (uint32_t)(row * ROWB + cc * 16);
        cp_async16(s0 + off, A + goA);
        size_t goB = (bRowBase + (size_t)row) * KT + k0 + cc * 8;
        cp_async16(s0 + A_BYTES + off, B + goB);
    }
}

__device__ __forceinline__ void gemm_mainloop(
    uint32_t sbase, int tx,
    const __half* A, const __half* B,
    const int* arow_tab, int aRowBase, int cnt, size_t bRowBase, int KT,
    float acc[4][4][4])
{
    const int NITER = KT / 32;
    int wid = tx >> 5;
    int lane = tx & 31;
    int wm = wid >> 2;
    int wn = wid & 3;
    int l15 = lane & 15;
    int l16 = lane >> 4;

    uint32_t aoff = (uint32_t)((wm * 64 + l15) * ROWB + l16 * 16);
    uint32_t boff = (uint32_t)(A_BYTES + (wn * 32 + l15) * ROWB + l16 * 16);

    load_stage(sbase, 0, tx, A, B, arow_tab, aRowBase, cnt, bRowBase, KT, 0);
    cp_commit();
    load_stage(sbase, 1, tx, A, B, arow_tab, aRowBase, cnt, bRowBase, KT, 32);
    cp_commit();

    for (int it = 0; it < NITER; it++) {
        if (it + 2 < NITER) {
            load_stage(sbase, (it + 2) % NSTAGE, tx, A, B,
                       arow_tab, aRowBase, cnt, bRowBase, KT, (it + 2) * 32);
        }
        cp_commit();
        cp_wait2();
        __syncthreads();

        uint32_t s0 = sbase + (uint32_t)(it % NSTAGE) * STG_BYTES;
        for (int kk = 0; kk < 2; kk++) {
            uint32_t ah[4][4], bb[2][4];
            for (int mt = 0; mt < 4; mt++) {
                uint32_t ad = s0 + aoff + (uint32_t)(mt * 16 * ROWB + kk * 32);
                ldm_x4(ah[mt][0], ah[mt][1], ah[mt][2], ah[mt][3], ad);
            }
            for (int g = 0; g < 2; g++) {
                uint32_t bd = s0 + boff + (uint32_t)(g * 16 * ROWB + kk * 32);
                ldm_x4(bb[g][0], bb[g][1], bb[g][2], bb[g][3], bd);
            }
            for (int mt = 0; mt < 4; mt++) {
                for (int nt = 0; nt < 4; nt++) {
                    int g = nt >> 1;
                    int p = nt & 1;
                    mma_f16(acc[mt][nt], ah[mt], bb[g][p], bb[g][p + 2]);
                }
            }
        }
    }
}

// GEMM1: A = g_xh gathered via row2tok (K=2048), N=2048 interleaved, silu -> g_inter
__global__ void __launch_bounds__(256, 2) gemm1_mma() {
    int e = blockIdx.z;
    int base = g_offsets[e];
    int cnt  = g_offsets[e + 1] - base;
    int row0 = blockIdx.y * 128;
    if (row0 >= cnt) return;
    int col0 = blockIdx.x * 128;

    extern __shared__ char smraw[];
    uint32_t sbase = smem_u32(smraw);
    int* toks = reinterpret_cast<int*>(smraw + TILE_SMEM);
    int tx = threadIdx.x;

    if (tx < 128) {
        int r = row0 + tx;
        toks[tx] = g_row2tok[base + ((r < cnt) ? r : (cnt - 1))];
    }
    __syncthreads();

    float acc[4][4][4];
    for (int a = 0; a < 4; a++)
        for (int b = 0; b < 4; b++)
            for (int c = 0; c < 4; c++) acc[a][b][c] = 0.f;

    size_t bRowBase = (size_t)e * 2048 + col0;
    gemm_mainloop(sbase, tx, g_xh, g_w1, toks, 0, cnt - row0, bRowBase, 2048, acc);

    int wid = tx >> 5;
    int lane = tx & 31;
    int wm = wid >> 2;
    int wn = wid & 3;
    int qrow = lane >> 2;
    int qcol = lane & 3;
    for (int mt = 0; mt < 4; mt++) {
        for (int nt = 0; nt < 4; nt++) {
            int r0 = row0 + wm * 64 + mt * 16 + qrow;
            int icol = ((col0 + wn * 32 + nt * 8) >> 1) + qcol;
            float* c = acc[mt][nt];
            if (r0 < cnt) {
                float v = c[0] / (1.f + __expf(-c[0])) * c[1];
                g_inter[(size_t)(base + r0) * M_DIM + icol] = __float2half(v);
            }
            int r1 = r0 + 8;
            if (r1 < cnt) {
                float v = c[2] / (1.f + __expf(-c[2])) * c[3];
                g_inter[(size_t)(base + r1) * M_DIM + icol] = __float2half(v);
            }
        }
    }
}

// GEMM2: A = g_inter (K=1024), N=2048, fp16 epilogue -> g_outsorted
__global__ void __launch_bounds__(256, 2) gemm2_mma() {
    int e = blockIdx.z;
    int base = g_offsets[e];
    int cnt  = g_offsets[e + 1] - base;
    int row0 = blockIdx.y * 128;
    if (row0 >= cnt) return;
    int col0 = blockIdx.x * 128;

    extern __shared__ char smraw[];
    uint32_t sbase = smem_u32(smraw);
    int tx = threadIdx.x;

    float acc[4][4][4];
    for (int a = 0; a < 4; a++)
        for (int b = 0; b < 4; b++)
            for (int c = 0; c < 4; c++) acc[a][b][c] = 0.f;

    size_t bRowBase = (size_t)e * 2048 + col0;
    gemm_mainloop(sbase, tx, g_inter, g_w2, (const int*)0,
                  base + row0, cnt - row0, bRowBase, 1024, acc);

    int wid = tx >> 5;
    int lane = tx & 31;
    int wm = wid >> 2;
    int wn = wid & 3;
    int qrow = lane >> 2;
    int qcol = lane & 3;
    for (int mt = 0; mt < 4; mt++) {
        for (int nt = 0; nt < 4; nt++) {
            int r0 = row0 + wm * 64 + mt * 16 + qrow;
            int colg = col0 + wn * 32 + nt * 8 + qcol * 2;
            float* c = acc[mt][nt];
            if (r0 < cnt) {
                __half2 v = __floats2half2_rn(c[0], c[1]);
                *reinterpret_cast<__half2*>(g_outsorted + (size_t)(base + r0) * D_DIM + colg) = v;
            }
            int r1 = r0 + 8;
            if (r1 < cnt) {
                __half2 v = __floats2half2_rn(c[2], c[3]);
                *reinterpret_cast<__half2*>(g_outsorted + (size_t)(base + r1) * D_DIM + colg) = v;
            }
        }
    }
}

// ---------------- combine (fp16 inputs) ----------------
__global__ void combine_k(float* __restrict__ out) {
    int t = blockIdx.x;
    float w0 = g_weight[t * 2 + 0];
    float w1 = g_weight[t * 2 + 1];
    const __half* p0 = g_outsorted + (size_t)g_pos[t * 2 + 0] * D_DIM;
    const __half* p1 = g_outsorted + (size_t)g_pos[t * 2 + 1] * D_DIM;
    float* o = out + (size_t)t * D_DIM;
    int d = threadIdx.x * 8;
    {
        uint4 ua = *reinterpret_cast<const uint4*>(p0 + d);
        uint4 ub = *reinterpret_cast<const uint4*>(p1 + d);
        const __half2* ha = reinterpret_cast<const __half2*>(&ua);
        const __half2* hb = reinterpret_cast<const __half2*>(&ub);
        float rr[8];
        for (int i = 0; i < 4; i++) {
            float2 fa = __half22float2(ha[i]);
            float2 fb = __half22float2(hb[i]);
            rr[2 * i + 0] = w0 * fa.x + w1 * fb.x;
            rr[2 * i + 1] = w0 * fa.y + w1 * fb.y;
        }
        *reinterpret_cast<float4*>(o + d)     = make_float4(rr[0], rr[1], rr[2], rr[3]);
        *reinterpret_cast<float4*>(o + d + 4) = make_float4(rr[4], rr[5], rr[6], rr[7]);
    }
}

// ---------------- launch ----------------
extern "C" void kernel_launch(void* const* d_in, const int* in_sizes, int n_in,
                              void* d_out, int out_size) {
    const float* x   = (const float*)d_in[0];
    const float* wg  = (const float*)d_in[1];
    const float* wi0 = (const float*)d_in[2];
    const float* wi1 = (const float*)d_in[3];
    const float* wo  = (const float*)d_in[4];
    float* out = (float*)d_out;

    cudaFuncSetAttribute(gemm1_mma, cudaFuncAttributeMaxDynamicSharedMemorySize, SMEM_REQ);
    cudaFuncSetAttribute(gemm2_mma, cudaFuncAttributeMaxDynamicSharedMemorySize, SMEM_REQ);

    init_k<<<1, 32>>>();
    router_k<<<T_TOK / 8, 256>>>(x, wg);
    scan_k<<<1, 32>>>();
    assign_k<<<NCOPIES / 256, 256>>>();

    convxtok_k<<<(T_TOK * D_DIM) / (256 * 8), 256>>>(x);
    convw1_k<<<dim3(D_DIM / 32, M_DIM / 32, E_NUM * 2), dim3(32, 8)>>>(wi0, wi1);
    convw2_k<<<dim3(M_DIM / 32, D_DIM / 32, E_NUM), dim3(32, 8)>>>(wo);

    dim3 g1(2 * M_DIM / 128, NCOPIES / 128, E_NUM);   // (16, 128, 8)
    gemm1_mma<<<g1, 256, SMEM_REQ>>>();

    dim3 g2(D_DIM / 128, NCOPIES / 128, E_NUM);       // (16, 128, 8)
    gemm2_mma<<<g2, 256, SMEM_REQ>>>();

    combine_k<<<T_TOK, 256>>>(out);
}